// round 9
// baseline (speedup 1.0000x reference)
#include <cuda_runtime.h>
#include <math.h>
#include <stddef.h>

#define Hh 1024
#define FH 4096
#define Bb 64
#define Tt 512
#define Mm 32768   // B*T

typedef unsigned long long ull;

// Scratch (device globals: no runtime allocation).
__device__ float g_xp[(size_t)Mm * FH];     // gate preactivations, current layer
__device__ float g_hseq[(size_t)Mm * Hh];   // hidden sequence, current layer
__device__ float g_hA[Bb * Hh];
__device__ float g_hB[Bb * Hh];
__device__ unsigned g_bar;                  // grid-barrier counter

__device__ __forceinline__ void ffma2(ull &c, ull a, ull b) {
    asm("fma.rn.f32x2 %0, %1, %2, %0;" : "+l"(c) : "l"(a), "l"(b));
}
__device__ __forceinline__ float pairsum(ull v) {
    return __uint_as_float((unsigned)v) + __uint_as_float((unsigned)(v >> 32));
}

// ---------------------------------------------------------------------------
// xp[m][n] = sum_k A[m][k]*W[n][k] + bi[n] + bh[n];  M=32768, N=4096.
// Block tile 128m x 64n, BK=32, 256 threads, 8m x 4n microtile.
// FFMA2 packed over k-pairs (even/odd k in one 64-bit acc) -> both operands
// are natural k-contiguous LDS.128, no splat, no duplication.
// SMEM rows stride 40 words, 4-float chunks XOR-swizzled by (row>>3)&7:
//   a-frag reads: warp-broadcast (row = f(ty) only)      -> 1 wf
//   b-frag reads: 16 distinct rows, swizzle spreads banks -> 2 wf
// Per SM per k-pair: crossbar ~128 cyc vs FFMA2 pipe 256 cyc -> FFMA2-bound.
// ---------------------------------------------------------------------------
#define SWZ(row, c) ((row) * 40 + ((((c) ^ (((row) >> 3) & 7))) << 2))

__global__ __launch_bounds__(256, 2) void gemm_xp(
    const float* __restrict__ Ax, int useX, int K,
    const float* __restrict__ W,
    const float* __restrict__ bi, const float* __restrict__ bh)
{
    const float* A = useX ? Ax : g_hseq;
    __shared__ __align__(16) float As[128 * 40];
    __shared__ __align__(16) float Bs[64 * 40];

    const int tid = threadIdx.x;
    const int tx = tid & 15, ty = tid >> 4;
    const int n0 = blockIdx.x * 64, m0 = blockIdx.y * 128;

    // global->smem load maps
    const int alr = tid >> 1, alk = (tid & 1) * 16;  // A: 128 rows x 32 k
    const int blr = tid >> 2, blk = (tid & 3) * 8;   // B:  64 rows x 32 k
    const float* Ap = A + (size_t)(m0 + alr) * K + alk;
    const float* Wp = W + (size_t)(n0 + blr) * K + blk;

    ull acc[8][4];
#pragma unroll
    for (int i = 0; i < 8; i++)
#pragma unroll
        for (int j = 0; j < 4; j++) acc[i][j] = 0ull;

    float4 ap[4], bp[2];
#pragma unroll
    for (int q = 0; q < 4; q++) ap[q] = *(const float4*)(Ap + q * 4);
#pragma unroll
    for (int q = 0; q < 2; q++) bp[q] = *(const float4*)(Wp + q * 4);

    const int ntiles = K >> 5;
    for (int kt = 0; kt < ntiles; kt++) {
        __syncthreads();
#pragma unroll
        for (int q = 0; q < 4; q++)
            *(float4*)&As[SWZ(alr, (tid & 1) * 4 + q)] = ap[q];
#pragma unroll
        for (int q = 0; q < 2; q++)
            *(float4*)&Bs[SWZ(blr, (tid & 3) * 2 + q)] = bp[q];
        __syncthreads();
        if (kt + 1 < ntiles) {
            const float* Ap2 = Ap + (kt + 1) * 32;
            const float* Wp2 = Wp + (kt + 1) * 32;
#pragma unroll
            for (int q = 0; q < 4; q++) ap[q] = *(const float4*)(Ap2 + q * 4);
#pragma unroll
            for (int q = 0; q < 2; q++) bp[q] = *(const float4*)(Wp2 + q * 4);
        }
        for (int c8 = 0; c8 < 8; c8++) {
            ulonglong2 bv[4];
#pragma unroll
            for (int j = 0; j < 4; j++)
                bv[j] = *(const ulonglong2*)&Bs[SWZ(tx * 4 + j, c8)];
#pragma unroll
            for (int i = 0; i < 8; i++) {
                ulonglong2 av = *(const ulonglong2*)&As[SWZ(ty * 8 + i, c8)];
#pragma unroll
                for (int j = 0; j < 4; j++) {
                    ffma2(acc[i][j], av.x, bv[j].x);
                    ffma2(acc[i][j], av.y, bv[j].y);
                }
            }
        }
    }

    float bias[4];
#pragma unroll
    for (int j = 0; j < 4; j++) {
        int n = n0 + tx * 4 + j;
        bias[j] = bi[n] + bh[n];
    }
#pragma unroll
    for (int i = 0; i < 8; i++) {
        float4 o;
        o.x = pairsum(acc[i][0]) + bias[0];
        o.y = pairsum(acc[i][1]) + bias[1];
        o.z = pairsum(acc[i][2]) + bias[2];
        o.w = pairsum(acc[i][3]) + bias[3];
        *(float4*)(g_xp + (size_t)(m0 + ty * 8 + i) * FH + n0 + tx * 4) = o;
    }
}

__global__ void init_state()
{
    int i = blockIdx.x * blockDim.x + threadIdx.x;
    if (i == 0) g_bar = 0u;
    if (i < Bb * Hh) g_hA[i] = 0.f;
}

// ---------------------------------------------------------------------------
// Persistent recurrence: one launch runs all 512 timesteps for one layer.
// 128 blocks x 256 threads (2 warps/SMSP for latency hiding), 1 block/SM.
// Block owns h-cols j0..j0+7 (32 gate rows); W slice (128KB) in SMEM for the
// whole layer. Thread (rq=col, bq 0..31) owns ALL FOUR gates of
// (col j0+rq, batches 2bq, 2bq+1): c stays in registers, no gate exchange.
// ---------------------------------------------------------------------------
#define WSTR 1028                       // W row stride (floats): conflict-free
#define HSTR 68                         // H tile row stride (floats)
#define SMEM_BYTES ((32 * WSTR + 2 * 64 * HSTR) * 4)

__global__ __launch_bounds__(256, 1) void lstm_persist(const float* __restrict__ Whh)
{
    extern __shared__ float smem[];
    float* Ws = smem;                   // [32][WSTR]
    float* Hsm = smem + 32 * WSTR;      // [2][64][HSTR]

    const int tid = threadIdx.x;
    const int j0 = blockIdx.x << 3;
    const int rq = tid & 7;             // column within block
    const int bq = tid >> 3;            // batch pair 0..31

    // Load W slice once: local row lw = gate*8 + col; global row = gate*1024+j0+col
    {
        const int lw = tid >> 3;                 // 0..31
        const int q8 = (tid & 7) * 128;          // k eighth
        const int grow = (lw >> 3) * Hh + j0 + (lw & 7);
        const float* wp = Whh + (size_t)grow * Hh + q8;
        float* wsp = Ws + lw * WSTR + q8;
#pragma unroll 8
        for (int c = 0; c < 32; c++)
            *(float4*)&wsp[c * 4] = *(const float4*)&wp[c * 4];
    }

    float c_reg[2] = {0.f, 0.f};

    // h tile-load map: 64 batches x 64 k per chunk, 4 float4 per thread
    const int hb = tid >> 2;
    const int hk = (tid & 3) * 16;

    for (int t = 0; t < Tt; t++) {
        const float* hp = (t & 1) ? g_hB : g_hA;
        float*       hn = (t & 1) ? g_hA : g_hB;

        // Prefetch xp for this step (independent of h -> hidden under GEMM)
        float xpv[4][2];
#pragma unroll
        for (int i = 0; i < 2; i++) {
            const float* xq = g_xp + ((size_t)(2 * bq + i) * Tt + t) * FH + j0 + rq;
#pragma unroll
            for (int g = 0; g < 4; g++) xpv[g][i] = xq[g * Hh];
        }

        ull acc[4][2];
#pragma unroll
        for (int g = 0; g < 4; g++)
#pragma unroll
            for (int i = 0; i < 2; i++) acc[g][i] = 0ull;

        // Prologue: prefetch h chunk 0 (ld.global.cg: L1 may be stale in-kernel)
        float4 pre[4];
        {
            const float* src = hp + (size_t)hb * Hh + hk;
#pragma unroll
            for (int q = 0; q < 4; q++) pre[q] = __ldcg((const float4*)(src + q * 4));
        }

        for (int kt = 0; kt < 16; kt++) {
            __syncthreads();
            float* hbuf = Hsm + (kt & 1) * (64 * HSTR);
            {
                float* dst = hbuf + hb * HSTR + hk;
#pragma unroll
                for (int q = 0; q < 4; q++) *(float4*)(dst + q * 4) = pre[q];
            }
            if (kt < 15) {
                const float* src = hp + (size_t)hb * Hh + (kt + 1) * 64 + hk;
#pragma unroll
                for (int q = 0; q < 4; q++) pre[q] = __ldcg((const float4*)(src + q * 4));
            }
            __syncthreads();
            const float* wk = Ws + kt * 64;
#pragma unroll
            for (int k4 = 0; k4 < 16; k4++) {
                ulonglong2 wv[4], hv[2];
#pragma unroll
                for (int g = 0; g < 4; g++)
                    wv[g] = *(const ulonglong2*)&wk[(g * 8 + rq) * WSTR + k4 * 4];
#pragma unroll
                for (int i = 0; i < 2; i++)
                    hv[i] = *(const ulonglong2*)&hbuf[(2 * bq + i) * HSTR + k4 * 4];
#pragma unroll
                for (int g = 0; g < 4; g++)
#pragma unroll
                    for (int i = 0; i < 2; i++) {
                        ffma2(acc[g][i], wv[g].x, hv[i].x);
                        ffma2(acc[g][i], wv[g].y, hv[i].y);
                    }
            }
        }

        // Elementwise LSTM update; c in registers.
#pragma unroll
        for (int i = 0; i < 2; i++) {
            const int b = 2 * bq + i;
            float gi = pairsum(acc[0][i]) + xpv[0][i];
            float gf = pairsum(acc[1][i]) + xpv[1][i];
            float gg = pairsum(acc[2][i]) + xpv[2][i];
            float go = pairsum(acc[3][i]) + xpv[3][i];
            float si = 1.f / (1.f + expf(-gi));
            float sf = 1.f / (1.f + expf(-gf));
            float so = 1.f / (1.f + expf(-go));
            float cn = sf * c_reg[i] + si * tanhf(gg);
            c_reg[i] = cn;
            float hv = so * tanhf(cn);
            hn[b * Hh + j0 + rq] = hv;
            g_hseq[((size_t)b * Tt + t) * Hh + j0 + rq] = hv;
        }

        // Grid barrier: monotonic counter, all 128 blocks resident.
        __threadfence();
        __syncthreads();
        if (tid == 0) {
            atomicAdd(&g_bar, 1u);
            const unsigned target = 128u * (unsigned)(t + 1);
            while (*(volatile unsigned*)&g_bar < target) { }
        }
        __syncthreads();
    }
}

__global__ void fc_kernel(const float* __restrict__ fw, const float* __restrict__ fb,
                          float* __restrict__ out)
{
    __shared__ float red[256];
    int b = blockIdx.x, tid = threadIdx.x;
    const float* h = g_hseq + ((size_t)b * Tt + (Tt - 1)) * Hh;
    float s = 0.f;
    for (int j = tid; j < Hh; j += 256) s += h[j] * fw[j];
    red[tid] = s;
    __syncthreads();
    for (int o = 128; o > 0; o >>= 1) {
        if (tid < o) red[tid] += red[tid + o];
        __syncthreads();
    }
    if (tid == 0) out[b] = red[0] + fb[0];
}

extern "C" void kernel_launch(void* const* d_in, const int* in_sizes, int n_in,
                              void* d_out, int out_size)
{
    const float* x      = (const float*)d_in[0];
    const float* Wih[3] = {(const float*)d_in[1], (const float*)d_in[2], (const float*)d_in[3]};
    const float* Whh    = (const float*)d_in[4];   // [3][4096][1024]
    const float* bih    = (const float*)d_in[5];   // [3][4096]
    const float* bhh    = (const float*)d_in[6];   // [3][4096]
    const float* fcw    = (const float*)d_in[7];   // [1][1024]
    const float* fcb    = (const float*)d_in[8];   // [1]
    float* out = (float*)d_out;

    cudaFuncSetAttribute(lstm_persist,
                         cudaFuncAttributeMaxDynamicSharedMemorySize, SMEM_BYTES);

    for (int l = 0; l < 3; l++) {
        int K = l ? Hh : 128;
        gemm_xp<<<dim3(64, 256), 256>>>(x, (l == 0) ? 1 : 0, K,
                                        Wih[l], bih + l * FH, bhh + l * FH);
        init_state<<<64, 1024>>>();
        lstm_persist<<<128, 256, SMEM_BYTES>>>(Whh + (size_t)l * FH * Hh);
    }
    fc_kernel<<<64, 256>>>(fcw, fcb, out);
}

// round 11
// speedup vs baseline: 1.0451x; 1.0451x over previous
#include <cuda_runtime.h>
#include <math.h>
#include <stdint.h>
#include <stddef.h>

#define Hh 1024
#define FH 4096
#define Bb 64
#define Tt 512
#define Mm 32768   // B*T

typedef unsigned long long ull;

// Scratch (device globals: no runtime allocation).
__device__ float g_xp[(size_t)Mm * FH];     // gate preactivations, current layer
__device__ float g_hseq[(size_t)Mm * Hh];   // hidden sequence, current layer
__device__ float g_Ahi[(size_t)Mm * Hh];    // tf32 split of A (hi)
__device__ float g_Alo[(size_t)Mm * Hh];    // tf32 split of A (lo)
__device__ float g_Whi[(size_t)FH * Hh];    // tf32 split of W_ih (hi)
__device__ float g_Wlo[(size_t)FH * Hh];    // tf32 split of W_ih (lo)
__device__ float g_hA[Bb * Hh];
__device__ float g_hB[Bb * Hh];
__device__ unsigned g_bar;                  // grid-barrier counter

__device__ __forceinline__ void ffma2(ull &c, ull a, ull b) {
    asm("fma.rn.f32x2 %0, %1, %2, %0;" : "+l"(c) : "l"(a), "l"(b));
}
__device__ __forceinline__ float pairsum(ull v) {
    return __uint_as_float((unsigned)v) + __uint_as_float((unsigned)(v >> 32));
}
__device__ __forceinline__ float tf32r(float x) {
    float r; asm("cvt.rna.tf32.f32 %0, %1;" : "=f"(r) : "f"(x)); return r;
}

// Warp-level tensor-core MMA (plain PTX ISA, works on generic compute_103):
// D(16x8) += A(16x8, row-major) * B(8x8, col-major), tf32 inputs, f32 accum.
__device__ __forceinline__ void mma_tf32(float* c, const uint32_t* a, const uint32_t* b) {
    asm volatile(
        "mma.sync.aligned.m16n8k8.row.col.f32.tf32.tf32.f32 "
        "{%0,%1,%2,%3}, {%4,%5,%6,%7}, {%8,%9}, {%0,%1,%2,%3};"
        : "+f"(c[0]), "+f"(c[1]), "+f"(c[2]), "+f"(c[3])
        : "r"(a[0]), "r"(a[1]), "r"(a[2]), "r"(a[3]), "r"(b[0]), "r"(b[1]));
}

// ---------------------------------------------------------------------------
// Split kernels: v -> (tf32(v), tf32(v - tf32(v)))
// ---------------------------------------------------------------------------
__global__ void split_A(const float* __restrict__ x, int useX, int n4)
{
    const float* src = useX ? x : g_hseq;
    int i = blockIdx.x * blockDim.x + threadIdx.x;
    if (i < n4) {
        float4 v = ((const float4*)src)[i];
        float4 h, l;
        h.x = tf32r(v.x); l.x = tf32r(v.x - h.x);
        h.y = tf32r(v.y); l.y = tf32r(v.y - h.y);
        h.z = tf32r(v.z); l.z = tf32r(v.z - h.z);
        h.w = tf32r(v.w); l.w = tf32r(v.w - h.w);
        ((float4*)g_Ahi)[i] = h; ((float4*)g_Alo)[i] = l;
    }
}
__global__ void split_W(const float* __restrict__ W, int n4)
{
    int i = blockIdx.x * blockDim.x + threadIdx.x;
    if (i < n4) {
        float4 v = ((const float4*)W)[i];
        float4 h, l;
        h.x = tf32r(v.x); l.x = tf32r(v.x - h.x);
        h.y = tf32r(v.y); l.y = tf32r(v.y - h.y);
        h.z = tf32r(v.z); l.z = tf32r(v.z - h.z);
        h.w = tf32r(v.w); l.w = tf32r(v.w - h.w);
        ((float4*)g_Whi)[i] = h; ((float4*)g_Wlo)[i] = l;
    }
}

// ---------------------------------------------------------------------------
// Tensor-core projection GEMM via warp mma.sync (3xTF32 split):
// g_xp[m][n] = sum_k A[m][k]*W[n][k] + bi[n] + bh[n]
// Block 128m x 64n, 8 warps (4m x 2n), warp tile 32x32 (2 m16 x 4 n8), BK=16.
// SMEM k8 cols permuted {0,4,1,5,2,6,3,7} so every fragment pair -- (a0,a2),
// (a1,a3), (b0,b1) -- is one aligned LDS.64. Row stride 10 words: STS 2-phase,
// LDS ~2-3 phase (bank math verified). Register-prefetch double buffering.
// ---------------------------------------------------------------------------
#define RS 10   // smem row stride (words)

__global__ __launch_bounds__(256) void gemm_tc32(int K,
    const float* __restrict__ bi, const float* __restrict__ bh)
{
    // As[sp][kc][128][RS], Ws[sp][kc][64][RS]
    __shared__ __align__(16) float As[2 * 2 * 128 * RS];
    __shared__ __align__(16) float Ws[2 * 2 * 64 * RS];

    const int tid = threadIdx.x;
    const int lane = tid & 31, wid = tid >> 5;
    const int wm = wid & 3, wn = wid >> 2;       // warp grid 4m x 2n
    const int m0 = blockIdx.y << 7, n0 = blockIdx.x << 6;

    // global-load maps
    const int arow = tid >> 1, akq = (tid & 1) * 8;   // A: 2 float4 per split
    const int wrow = tid >> 2, wkq = (tid & 3) * 4;   // W: 1 float4 per split
    const float* pA[2] = { g_Ahi + (size_t)(m0 + arow) * K + akq,
                           g_Alo + (size_t)(m0 + arow) * K + akq };
    const float* pW[2] = { g_Whi + (size_t)(n0 + wrow) * K + wkq,
                           g_Wlo + (size_t)(n0 + wrow) * K + wkq };

    float acc[2][4][4];
#pragma unroll
    for (int mt = 0; mt < 2; mt++)
#pragma unroll
        for (int nt = 0; nt < 4; nt++)
#pragma unroll
            for (int q = 0; q < 4; q++) acc[mt][nt][q] = 0.f;

    float4 pa[2][2], pw[2];
#pragma unroll
    for (int sp = 0; sp < 2; sp++) {
        pa[sp][0] = *(const float4*)(pA[sp]);
        pa[sp][1] = *(const float4*)(pA[sp] + 4);
        pw[sp]    = *(const float4*)(pW[sp]);
    }

    const int nch = K >> 4;
    for (int ch = 0; ch < nch; ch++) {
        __syncthreads();
        // Store with k8 permutation: col c -> pos (c<4 ? 2c : 2(c-4)+1).
        // float4 at k-base kb (kb%4==0): kc=kb>>3, pos_j = 2j + (kb&4 ? 1 : 0).
#pragma unroll
        for (int sp = 0; sp < 2; sp++) {
#pragma unroll
            for (int f = 0; f < 2; f++) {
                const int kb = akq + f * 4;
                const int kc = kb >> 3, podd = (kb & 4) ? 1 : 0;
                float* dst = &As[((sp * 2 + kc) * 128 + arow) * RS + podd];
                const float* v = (const float*)&pa[sp][f];
                dst[0] = v[0]; dst[2] = v[1]; dst[4] = v[2]; dst[6] = v[3];
            }
            {
                const int kc = wkq >> 3, podd = (wkq & 4) ? 1 : 0;
                float* dst = &Ws[((sp * 2 + kc) * 64 + wrow) * RS + podd];
                const float* v = (const float*)&pw[sp];
                dst[0] = v[0]; dst[2] = v[1]; dst[4] = v[2]; dst[6] = v[3];
            }
        }
        __syncthreads();
        if (ch + 1 < nch) {
#pragma unroll
            for (int sp = 0; sp < 2; sp++) {
                pa[sp][0] = *(const float4*)(pA[sp] + (ch + 1) * 16);
                pa[sp][1] = *(const float4*)(pA[sp] + (ch + 1) * 16 + 4);
                pw[sp]    = *(const float4*)(pW[sp] + (ch + 1) * 16);
            }
        }
#pragma unroll
        for (int kc = 0; kc < 2; kc++) {
            uint32_t af[2][2][4];   // [split][mtile][a0..a3]
            uint32_t bf[2][4][2];   // [split][ntile][b0,b1]
            const int co = 2 * (lane & 3);
#pragma unroll
            for (int sp = 0; sp < 2; sp++) {
#pragma unroll
                for (int mt = 0; mt < 2; mt++) {
                    const int mr = wm * 32 + mt * 16 + (lane >> 2);
                    float2 lo = *(const float2*)&As[((sp * 2 + kc) * 128 + mr) * RS + co];
                    float2 hi = *(const float2*)&As[((sp * 2 + kc) * 128 + mr + 8) * RS + co];
                    af[sp][mt][0] = __float_as_uint(lo.x);
                    af[sp][mt][2] = __float_as_uint(lo.y);
                    af[sp][mt][1] = __float_as_uint(hi.x);
                    af[sp][mt][3] = __float_as_uint(hi.y);
                }
#pragma unroll
                for (int nt = 0; nt < 4; nt++) {
                    const int nr = wn * 32 + nt * 8 + (lane >> 2);
                    float2 bv = *(const float2*)&Ws[((sp * 2 + kc) * 64 + nr) * RS + co];
                    bf[sp][nt][0] = __float_as_uint(bv.x);
                    bf[sp][nt][1] = __float_as_uint(bv.y);
                }
            }
#pragma unroll
            for (int mt = 0; mt < 2; mt++)
#pragma unroll
                for (int nt = 0; nt < 4; nt++) {
                    mma_tf32(acc[mt][nt], af[0][mt], bf[0][nt]);  // hi*hi
                    mma_tf32(acc[mt][nt], af[0][mt], bf[1][nt]);  // hi*lo
                    mma_tf32(acc[mt][nt], af[1][mt], bf[0][nt]);  // lo*hi
                }
        }
    }

    // Epilogue: c0/c1 -> (m, n/n+1), c2/c3 -> (m+8, n/n+1). float2 stores.
#pragma unroll
    for (int mt = 0; mt < 2; mt++) {
        const int m = m0 + wm * 32 + mt * 16 + (lane >> 2);
#pragma unroll
        for (int nt = 0; nt < 4; nt++) {
            const int n = n0 + wn * 32 + nt * 8 + 2 * (lane & 3);
            const float b0 = __ldg(&bi[n]) + __ldg(&bh[n]);
            const float b1 = __ldg(&bi[n + 1]) + __ldg(&bh[n + 1]);
            float2 o0 = make_float2(acc[mt][nt][0] + b0, acc[mt][nt][1] + b1);
            float2 o1 = make_float2(acc[mt][nt][2] + b0, acc[mt][nt][3] + b1);
            *(float2*)(g_xp + (size_t)m * FH + n)       = o0;
            *(float2*)(g_xp + (size_t)(m + 8) * FH + n) = o1;
        }
    }
}

__global__ void init_state()
{
    int i = blockIdx.x * blockDim.x + threadIdx.x;
    if (i == 0) g_bar = 0u;
    if (i < Bb * Hh) g_hA[i] = 0.f;
}

// ---------------------------------------------------------------------------
// Persistent recurrence (exact R6 version, part of the 61.6ms best run).
// ---------------------------------------------------------------------------
#define WSTR 1028
#define HSTR 68
#define SMEM_BYTES ((32 * WSTR + 2 * 64 * HSTR) * 4)

__global__ __launch_bounds__(128, 1) void lstm_persist(const float* __restrict__ Whh)
{
    extern __shared__ float smem[];
    float* Ws = smem;                   // [32][WSTR]
    float* Hsm = smem + 32 * WSTR;      // [2][64][HSTR]

    const int tid = threadIdx.x;
    const int j0 = blockIdx.x << 3;
    const int rq = tid & 7;
    const int bq = tid >> 3;

    {
        const int lw = tid >> 2;
        const int q4 = (tid & 3) * 256;
        const int grow = (lw >> 3) * Hh + j0 + (lw & 7);
        const float* wp = Whh + (size_t)grow * Hh + q4;
        float* wsp = Ws + lw * WSTR + q4;
#pragma unroll 8
        for (int c = 0; c < 64; c++)
            *(float4*)&wsp[c * 4] = *(const float4*)&wp[c * 4];
    }

    float c_reg[4] = {0.f, 0.f, 0.f, 0.f};
    const int hb = tid >> 1;
    const int hk = (tid & 1) * 32;

    for (int t = 0; t < Tt; t++) {
        const float* hp = (t & 1) ? g_hB : g_hA;
        float*       hn = (t & 1) ? g_hA : g_hB;

        float xpv[4][4];
#pragma unroll
        for (int i = 0; i < 4; i++) {
            const float* xq = g_xp + ((size_t)(4 * bq + i) * Tt + t) * FH + j0 + rq;
#pragma unroll
            for (int j = 0; j < 4; j++) xpv[j][i] = xq[j * Hh];
        }

        ull acc[4][4];
#pragma unroll
        for (int j = 0; j < 4; j++)
#pragma unroll
            for (int i = 0; i < 4; i++) acc[j][i] = 0ull;

        float4 pre[8];
        {
            const float* src = hp + (size_t)hb * Hh + hk;
#pragma unroll
            for (int q = 0; q < 8; q++) pre[q] = __ldcg((const float4*)(src + q * 4));
        }

        for (int kt = 0; kt < 16; kt++) {
            __syncthreads();
            float* hbuf = Hsm + (kt & 1) * (64 * HSTR);
            {
                float* dst = hbuf + hb * HSTR + hk;
#pragma unroll
                for (int q = 0; q < 8; q++) *(float4*)(dst + q * 4) = pre[q];
            }
            if (kt < 15) {
                const float* src = hp + (size_t)hb * Hh + (kt + 1) * 64 + hk;
#pragma unroll
                for (int q = 0; q < 8; q++) pre[q] = __ldcg((const float4*)(src + q * 4));
            }
            __syncthreads();
            const float* wk = Ws + kt * 64;
#pragma unroll
            for (int k4 = 0; k4 < 16; k4++) {
                ulonglong2 wv[4], hv[4];
#pragma unroll
                for (int j = 0; j < 4; j++)
                    wv[j] = *(const ulonglong2*)&wk[(j * 8 + rq) * WSTR + k4 * 4];
#pragma unroll
                for (int i = 0; i < 4; i++)
                    hv[i] = *(const ulonglong2*)&hbuf[(4 * bq + i) * HSTR + k4 * 4];
#pragma unroll
                for (int j = 0; j < 4; j++)
#pragma unroll
                    for (int i = 0; i < 4; i++) {
                        ffma2(acc[j][i], wv[j].x, hv[i].x);
                        ffma2(acc[j][i], wv[j].y, hv[i].y);
                    }
            }
        }

#pragma unroll
        for (int i = 0; i < 4; i++) {
            const int b = 4 * bq + i;
            float gi = pairsum(acc[0][i]) + xpv[0][i];
            float gf = pairsum(acc[1][i]) + xpv[1][i];
            float gg = pairsum(acc[2][i]) + xpv[2][i];
            float go = pairsum(acc[3][i]) + xpv[3][i];
            float si = 1.f / (1.f + expf(-gi));
            float sf = 1.f / (1.f + expf(-gf));
            float so = 1.f / (1.f + expf(-go));
            float cn = sf * c_reg[i] + si * tanhf(gg);
            c_reg[i] = cn;
            float hv = so * tanhf(cn);
            hn[b * Hh + j0 + rq] = hv;
            g_hseq[((size_t)b * Tt + t) * Hh + j0 + rq] = hv;
        }

        __threadfence();
        __syncthreads();
        if (tid == 0) {
            atomicAdd(&g_bar, 1u);
            const unsigned target = 128u * (unsigned)(t + 1);
            while (*(volatile unsigned*)&g_bar < target) { }
        }
        __syncthreads();
    }
}

__global__ void fc_kernel(const float* __restrict__ fw, const float* __restrict__ fb,
                          float* __restrict__ out)
{
    __shared__ float red[256];
    int b = blockIdx.x, tid = threadIdx.x;
    const float* h = g_hseq + ((size_t)b * Tt + (Tt - 1)) * Hh;
    float s = 0.f;
    for (int j = tid; j < Hh; j += 256) s += h[j] * fw[j];
    red[tid] = s;
    __syncthreads();
    for (int o = 128; o > 0; o >>= 1) {
        if (tid < o) red[tid] += red[tid + o];
        __syncthreads();
    }
    if (tid == 0) out[b] = red[0] + fb[0];
}

extern "C" void kernel_launch(void* const* d_in, const int* in_sizes, int n_in,
                              void* d_out, int out_size)
{
    const float* x      = (const float*)d_in[0];
    const float* Wih[3] = {(const float*)d_in[1], (const float*)d_in[2], (const float*)d_in[3]};
    const float* Whh    = (const float*)d_in[4];   // [3][4096][1024]
    const float* bih    = (const float*)d_in[5];   // [3][4096]
    const float* bhh    = (const float*)d_in[6];   // [3][4096]
    const float* fcw    = (const float*)d_in[7];   // [1][1024]
    const float* fcb    = (const float*)d_in[8];   // [1]
    float* out = (float*)d_out;

    cudaFuncSetAttribute(lstm_persist,
                         cudaFuncAttributeMaxDynamicSharedMemorySize, SMEM_BYTES);

    for (int l = 0; l < 3; l++) {
        const int K = l ? Hh : 128;
        const int nA4 = Mm * K / 4;
        const int nW4 = FH * K / 4;
        split_A<<<(nA4 + 255) / 256, 256>>>(x, (l == 0) ? 1 : 0, nA4);
        split_W<<<(nW4 + 255) / 256, 256>>>(Wih[l], nW4);
        gemm_tc32<<<dim3(64, 256), 256>>>(K, bih + l * FH, bhh + l * FH);
        init_state<<<64, 1024>>>();
        lstm_persist<<<128, 128, SMEM_BYTES>>>(Whh + (size_t)l * FH * Hh);
    }
    fc_kernel<<<64, 256>>>(fcw, fcb, out);
}

// round 12
// speedup vs baseline: 1.1943x; 1.1428x over previous
#include <cuda_runtime.h>
#include <cuda_bf16.h>
#include <math.h>
#include <stdint.h>
#include <stddef.h>

#define Hh 1024
#define FH 4096
#define Bb 64
#define Tt 512
#define Mm 32768   // B*T

typedef unsigned long long ull;

// Scratch (device globals: no runtime allocation).
__device__ float g_xp[(size_t)Mm * FH];         // gate preactivations
__device__ float g_hseq[(size_t)Mm * Hh];       // hidden sequence, current layer
__device__ unsigned g_Ahi[(size_t)Mm * Hh / 2]; // bf16-pair split of A (hi)
__device__ unsigned g_Alo[(size_t)Mm * Hh / 2]; // bf16-pair split of A (lo)
__device__ unsigned g_Whi[(size_t)FH * Hh / 2]; // bf16-pair split of W_ih (hi)
__device__ unsigned g_Wlo[(size_t)FH * Hh / 2]; // bf16-pair split of W_ih (lo)
__device__ float g_hA[Bb * Hh];
__device__ float g_hB[Bb * Hh];
__device__ unsigned g_bar;                      // grid-barrier counter

__device__ __forceinline__ void ffma2(ull &c, ull a, ull b) {
    asm("fma.rn.f32x2 %0, %1, %2, %0;" : "+l"(c) : "l"(a), "l"(b));
}
__device__ __forceinline__ float pairsum(ull v) {
    return __uint_as_float((unsigned)v) + __uint_as_float((unsigned)(v >> 32));
}

// bf16 m16n8k16 warp MMA (plain PTX ISA, sm_80+, fine through compute_103):
// D(16x8) += A(16x16 row) * B(8x16 col), f32 accum.
__device__ __forceinline__ void mma_bf16(float* c, const uint32_t* a, const uint32_t* b) {
    asm volatile(
        "mma.sync.aligned.m16n8k16.row.col.f32.bf16.bf16.f32 "
        "{%0,%1,%2,%3}, {%4,%5,%6,%7}, {%8,%9}, {%0,%1,%2,%3};"
        : "+f"(c[0]), "+f"(c[1]), "+f"(c[2]), "+f"(c[3])
        : "r"(a[0]), "r"(a[1]), "r"(a[2]), "r"(a[3]), "r"(b[0]), "r"(b[1]));
}

__device__ __forceinline__ unsigned packbf(float a, float b, float& ra, float& rb) {
    __nv_bfloat16 ha = __float2bfloat16_rn(a);
    __nv_bfloat16 hb = __float2bfloat16_rn(b);
    ra = a - __bfloat162float(ha);
    rb = b - __bfloat162float(hb);
    return (unsigned)__bfloat16_as_ushort(ha) |
           ((unsigned)__bfloat16_as_ushort(hb) << 16);
}
__device__ __forceinline__ unsigned packbf2(float a, float b) {
    __nv_bfloat16 ha = __float2bfloat16_rn(a);
    __nv_bfloat16 hb = __float2bfloat16_rn(b);
    return (unsigned)__bfloat16_as_ushort(ha) |
           ((unsigned)__bfloat16_as_ushort(hb) << 16);
}

// ---------------------------------------------------------------------------
// Split kernels: v -> (bf16(v), bf16(v - bf16(v))), packed as k-pairs.
// ---------------------------------------------------------------------------
__global__ void split_A(const float* __restrict__ x, int useX, int n4)
{
    const float* src = useX ? x : g_hseq;
    int i = blockIdx.x * blockDim.x + threadIdx.x;
    if (i < n4) {
        float4 v = ((const float4*)src)[i];
        float rx, ry, rz, rw;
        uint2 h, l;
        h.x = packbf(v.x, v.y, rx, ry);
        h.y = packbf(v.z, v.w, rz, rw);
        l.x = packbf2(rx, ry);
        l.y = packbf2(rz, rw);
        ((uint2*)g_Ahi)[i] = h;
        ((uint2*)g_Alo)[i] = l;
    }
}
__global__ void split_W(const float* __restrict__ W, int n4)
{
    int i = blockIdx.x * blockDim.x + threadIdx.x;
    if (i < n4) {
        float4 v = ((const float4*)W)[i];
        float rx, ry, rz, rw;
        uint2 h, l;
        h.x = packbf(v.x, v.y, rx, ry);
        h.y = packbf(v.z, v.w, rz, rw);
        l.x = packbf2(rx, ry);
        l.y = packbf2(rz, rw);
        ((uint2*)g_Whi)[i] = h;
        ((uint2*)g_Wlo)[i] = l;
    }
}

// ---------------------------------------------------------------------------
// Projection GEMM via bf16 m16n8k16 mma.sync (2-term split, 3 products):
// g_xp[m][n] = sum_k A[m][k]*W[n][k] + bi[n] + bh[n]
// Block 128m x 64n, 8 warps (4m x 2n), warp tile 32x32, chunk = 32 k-elements
// (16 packed words). SMEM word-columns permuted {0,4,1,5,2,6,3,7} so each
// fragment pair -- (a0,a2), (a1,a3), (b0,b1) -- is one aligned LDS.64.
// Same addressing as the validated R11 tf32 kernel; 2x K-depth per MMA.
// ---------------------------------------------------------------------------
#define RS 10   // smem row stride (words)

__global__ __launch_bounds__(256) void gemm_bf(int K,
    const float* __restrict__ bi, const float* __restrict__ bh)
{
    // As[sp][kc][128][RS], Ws[sp][kc][64][RS]  (words = bf16 k-pairs)
    __shared__ __align__(16) unsigned As[2 * 2 * 128 * RS];
    __shared__ __align__(16) unsigned Ws[2 * 2 * 64 * RS];

    const int tid = threadIdx.x;
    const int lane = tid & 31, wid = tid >> 5;
    const int wm = wid & 3, wn = wid >> 2;       // warp grid 4m x 2n
    const int m0 = blockIdx.y << 7, n0 = blockIdx.x << 6;
    const int Kw = K >> 1;                       // row length in words

    // global-load maps (word units)
    const int arow = tid >> 1, akq = (tid & 1) * 8;   // A: 2 uint4 per split
    const int wrow = tid >> 2, wkq = (tid & 3) * 4;   // W: 1 uint4 per split
    const unsigned* pA[2] = { g_Ahi + (size_t)(m0 + arow) * Kw + akq,
                              g_Alo + (size_t)(m0 + arow) * Kw + akq };
    const unsigned* pW[2] = { g_Whi + (size_t)(n0 + wrow) * Kw + wkq,
                              g_Wlo + (size_t)(n0 + wrow) * Kw + wkq };

    float acc[2][4][4];
#pragma unroll
    for (int mt = 0; mt < 2; mt++)
#pragma unroll
        for (int nt = 0; nt < 4; nt++)
#pragma unroll
            for (int q = 0; q < 4; q++) acc[mt][nt][q] = 0.f;

    uint4 pa[2][2], pw[2];
#pragma unroll
    for (int sp = 0; sp < 2; sp++) {
        pa[sp][0] = *(const uint4*)(pA[sp]);
        pa[sp][1] = *(const uint4*)(pA[sp] + 4);
        pw[sp]    = *(const uint4*)(pW[sp]);
    }

    const int nch = K >> 5;                      // 32 elements = 16 words/chunk
    for (int ch = 0; ch < nch; ch++) {
        __syncthreads();
        // Store with word-col permutation: wc -> (wc<4 ? 2wc : 2(wc-4)+1).
#pragma unroll
        for (int sp = 0; sp < 2; sp++) {
#pragma unroll
            for (int f = 0; f < 2; f++) {
                const int kb = akq + f * 4;
                const int kc = kb >> 3, podd = (kb & 4) ? 1 : 0;
                unsigned* dst = &As[((sp * 2 + kc) * 128 + arow) * RS + podd];
                const unsigned* v = (const unsigned*)&pa[sp][f];
                dst[0] = v[0]; dst[2] = v[1]; dst[4] = v[2]; dst[6] = v[3];
            }
            {
                const int kc = wkq >> 3, podd = (wkq & 4) ? 1 : 0;
                unsigned* dst = &Ws[((sp * 2 + kc) * 64 + wrow) * RS + podd];
                const unsigned* v = (const unsigned*)&pw[sp];
                dst[0] = v[0]; dst[2] = v[1]; dst[4] = v[2]; dst[6] = v[3];
            }
        }
        __syncthreads();
        if (ch + 1 < nch) {
#pragma unroll
            for (int sp = 0; sp < 2; sp++) {
                pa[sp][0] = *(const uint4*)(pA[sp] + (ch + 1) * 16);
                pa[sp][1] = *(const uint4*)(pA[sp] + (ch + 1) * 16 + 4);
                pw[sp]    = *(const uint4*)(pW[sp] + (ch + 1) * 16);
            }
        }
#pragma unroll
        for (int kc = 0; kc < 2; kc++) {
            uint32_t af[2][2][4];   // [split][mtile][a0..a3]
            uint32_t bf[2][4][2];   // [split][ntile][b0,b1]
            const int co = 2 * (lane & 3);
#pragma unroll
            for (int sp = 0; sp < 2; sp++) {
#pragma unroll
                for (int mt = 0; mt < 2; mt++) {
                    const int mr = wm * 32 + mt * 16 + (lane >> 2);
                    uint2 lo = *(const uint2*)&As[((sp * 2 + kc) * 128 + mr) * RS + co];
                    uint2 hi = *(const uint2*)&As[((sp * 2 + kc) * 128 + mr + 8) * RS + co];
                    af[sp][mt][0] = lo.x;
                    af[sp][mt][2] = lo.y;
                    af[sp][mt][1] = hi.x;
                    af[sp][mt][3] = hi.y;
                }
#pragma unroll
                for (int nt = 0; nt < 4; nt++) {
                    const int nr = wn * 32 + nt * 8 + (lane >> 2);
                    uint2 bv = *(const uint2*)&Ws[((sp * 2 + kc) * 64 + nr) * RS + co];
                    bf[sp][nt][0] = bv.x;
                    bf[sp][nt][1] = bv.y;
                }
            }
#pragma unroll
            for (int mt = 0; mt < 2; mt++)
#pragma unroll
                for (int nt = 0; nt < 4; nt++) {
                    mma_bf16(acc[mt][nt], af[0][mt], bf[0][nt]);  // hi*hi
                    mma_bf16(acc[mt][nt], af[0][mt], bf[1][nt]);  // hi*lo
                    mma_bf16(acc[mt][nt], af[1][mt], bf[0][nt]);  // lo*hi
                }
        }
    }

    // Epilogue: c0/c1 -> (m, n/n+1), c2/c3 -> (m+8, n/n+1). float2 stores.
#pragma unroll
    for (int mt = 0; mt < 2; mt++) {
        const int m = m0 + wm * 32 + mt * 16 + (lane >> 2);
#pragma unroll
        for (int nt = 0; nt < 4; nt++) {
            const int n = n0 + wn * 32 + nt * 8 + 2 * (lane & 3);
            const float b0 = __ldg(&bi[n]) + __ldg(&bh[n]);
            const float b1 = __ldg(&bi[n + 1]) + __ldg(&bh[n + 1]);
            float2 o0 = make_float2(acc[mt][nt][0] + b0, acc[mt][nt][1] + b1);
            float2 o1 = make_float2(acc[mt][nt][2] + b0, acc[mt][nt][3] + b1);
            *(float2*)(g_xp + (size_t)m * FH + n)       = o0;
            *(float2*)(g_xp + (size_t)(m + 8) * FH + n) = o1;
        }
    }
}

__global__ void init_state()
{
    int i = blockIdx.x * blockDim.x + threadIdx.x;
    if (i == 0) g_bar = 0u;
    if (i < Bb * Hh) g_hA[i] = 0.f;
}

// ---------------------------------------------------------------------------
// Persistent recurrence (exact R6 version, part of the 61.6ms best run).
// ---------------------------------------------------------------------------
#define WSTR 1028
#define HSTR 68
#define SMEM_BYTES ((32 * WSTR + 2 * 64 * HSTR) * 4)

__global__ __launch_bounds__(128, 1) void lstm_persist(const float* __restrict__ Whh)
{
    extern __shared__ float smem[];
    float* Ws = smem;                   // [32][WSTR]
    float* Hsm = smem + 32 * WSTR;      // [2][64][HSTR]

    const int tid = threadIdx.x;
    const int j0 = blockIdx.x << 3;
    const int rq = tid & 7;
    const int bq = tid >> 3;

    {
        const int lw = tid >> 2;
        const int q4 = (tid & 3) * 256;
        const int grow = (lw >> 3) * Hh + j0 + (lw & 7);
        const float* wp = Whh + (size_t)grow * Hh + q4;
        float* wsp = Ws + lw * WSTR + q4;
#pragma unroll 8
        for (int c = 0; c < 64; c++)
            *(float4*)&wsp[c * 4] = *(const float4*)&wp[c * 4];
    }

    float c_reg[4] = {0.f, 0.f, 0.f, 0.f};
    const int hb = tid >> 1;
    const int hk = (tid & 1) * 32;

    for (int t = 0; t < Tt; t++) {
        const float* hp = (t & 1) ? g_hB : g_hA;
        float*       hn = (t & 1) ? g_hA : g_hB;

        float xpv[4][4];
#pragma unroll
        for (int i = 0; i < 4; i++) {
            const float* xq = g_xp + ((size_t)(4 * bq + i) * Tt + t) * FH + j0 + rq;
#pragma unroll
            for (int j = 0; j < 4; j++) xpv[j][i] = xq[j * Hh];
        }

        ull acc[4][4];
#pragma unroll
        for (int j = 0; j < 4; j++)
#pragma unroll
            for (int i = 0; i < 4; i++) acc[j][i] = 0ull;

        float4 pre[8];
        {
            const float* src = hp + (size_t)hb * Hh + hk;
#pragma unroll
            for (int q = 0; q < 8; q++) pre[q] = __ldcg((const float4*)(src + q * 4));
        }

        for (int kt = 0; kt < 16; kt++) {
            __syncthreads();
            float* hbuf = Hsm + (kt & 1) * (64 * HSTR);
            {
                float* dst = hbuf + hb * HSTR + hk;
#pragma unroll
                for (int q = 0; q < 8; q++) *(float4*)(dst + q * 4) = pre[q];
            }
            if (kt < 15) {
                const float* src = hp + (size_t)hb * Hh + (kt + 1) * 64 + hk;
#pragma unroll
                for (int q = 0; q < 8; q++) pre[q] = __ldcg((const float4*)(src + q * 4));
            }
            __syncthreads();
            const float* wk = Ws + kt * 64;
#pragma unroll
            for (int k4 = 0; k4 < 16; k4++) {
                ulonglong2 wv[4], hv[4];
#pragma unroll
                for (int j = 0; j < 4; j++)
                    wv[j] = *(const ulonglong2*)&wk[(j * 8 + rq) * WSTR + k4 * 4];
#pragma unroll
                for (int i = 0; i < 4; i++)
                    hv[i] = *(const ulonglong2*)&hbuf[(4 * bq + i) * HSTR + k4 * 4];
#pragma unroll
                for (int j = 0; j < 4; j++)
#pragma unroll
                    for (int i = 0; i < 4; i++) {
                        ffma2(acc[j][i], wv[j].x, hv[i].x);
                        ffma2(acc[j][i], wv[j].y, hv[i].y);
                    }
            }
        }

#pragma unroll
        for (int i = 0; i < 4; i++) {
            const int b = 4 * bq + i;
            float gi = pairsum(acc[0][i]) + xpv[0][i];
            float gf = pairsum(acc[1][i]) + xpv[1][i];
            float gg = pairsum(acc[2][i]) + xpv[2][i];
            float go = pairsum(acc[3][i]) + xpv[3][i];
            float si = 1.f / (1.f + expf(-gi));
            float sf = 1.f / (1.f + expf(-gf));
            float so = 1.f / (1.f + expf(-go));
            float cn = sf * c_reg[i] + si * tanhf(gg);
            c_reg[i] = cn;
            float hv = so * tanhf(cn);
            hn[b * Hh + j0 + rq] = hv;
            g_hseq[((size_t)b * Tt + t) * Hh + j0 + rq] = hv;
        }

        __threadfence();
        __syncthreads();
        if (tid == 0) {
            atomicAdd(&g_bar, 1u);
            const unsigned target = 128u * (unsigned)(t + 1);
            while (*(volatile unsigned*)&g_bar < target) { }
        }
        __syncthreads();
    }
}

__global__ void fc_kernel(const float* __restrict__ fw, const float* __restrict__ fb,
                          float* __restrict__ out)
{
    __shared__ float red[256];
    int b = blockIdx.x, tid = threadIdx.x;
    const float* h = g_hseq + ((size_t)b * Tt + (Tt - 1)) * Hh;
    float s = 0.f;
    for (int j = tid; j < Hh; j += 256) s += h[j] * fw[j];
    red[tid] = s;
    __syncthreads();
    for (int o = 128; o > 0; o >>= 1) {
        if (tid < o) red[tid] += red[tid + o];
        __syncthreads();
    }
    if (tid == 0) out[b] = red[0] + fb[0];
}

extern "C" void kernel_launch(void* const* d_in, const int* in_sizes, int n_in,
                              void* d_out, int out_size)
{
    const float* x      = (const float*)d_in[0];
    const float* Wih[3] = {(const float*)d_in[1], (const float*)d_in[2], (const float*)d_in[3]};
    const float* Whh    = (const float*)d_in[4];   // [3][4096][1024]
    const float* bih    = (const float*)d_in[5];   // [3][4096]
    const float* bhh    = (const float*)d_in[6];   // [3][4096]
    const float* fcw    = (const float*)d_in[7];   // [1][1024]
    const float* fcb    = (const float*)d_in[8];   // [1]
    float* out = (float*)d_out;

    cudaFuncSetAttribute(lstm_persist,
                         cudaFuncAttributeMaxDynamicSharedMemorySize, SMEM_BYTES);

    for (int l = 0; l < 3; l++) {
        const int K = l ? Hh : 128;
        const int nA4 = Mm * K / 4;
        const int nW4 = FH * K / 4;
        split_A<<<(nA4 + 255) / 256, 256>>>(x, (l == 0) ? 1 : 0, nA4);
        split_W<<<(nW4 + 255) / 256, 256>>>(Wih[l], nW4);
        gemm_bf<<<dim3(64, 256), 256>>>(K, bih + l * FH, bhh + l * FH);
        init_state<<<64, 1024>>>();
        lstm_persist<<<128, 128, SMEM_BYTES>>>(Whh + (size_t)l * FH * Hh);
    }
    fc_kernel<<<64, 256>>>(fcw, fcb, out);
}

// round 14
// speedup vs baseline: 1.7704x; 1.4824x over previous
#include <cuda_runtime.h>
#include <cuda_bf16.h>
#include <math.h>
#include <stdint.h>
#include <stddef.h>

#define Hh 1024
#define FH 4096
#define Bb 64
#define Tt 512
#define Mm 32768   // B*T

// Scratch (device globals: no runtime allocation).
__device__ float g_xp[(size_t)Mm * FH];             // gate preactivations
__device__ unsigned g_seqHi[(size_t)Mm * Hh / 2];   // bf16 hidden seq (hi), word-packed
__device__ unsigned g_seqLo[(size_t)Mm * Hh / 2];   // bf16 hidden seq (lo)
__device__ unsigned g_Whi[(size_t)FH * Hh / 2];     // bf16-pair split of W_ih (hi)
__device__ unsigned g_Wlo[(size_t)FH * Hh / 2];     // bf16-pair split of W_ih (lo)
__device__ unsigned g_shHi[2 * 32768];              // per-step h (hi), 2 buffers
__device__ unsigned g_shLo[2 * 32768];              // per-step h (lo)
__device__ unsigned g_bar;                          // grid-barrier counter

// bf16 m16n8k16 warp MMA (plain PTX ISA, compiles on compute_103):
__device__ __forceinline__ void mma_bf16(float* c, const uint32_t* a, const uint32_t* b) {
    asm volatile(
        "mma.sync.aligned.m16n8k16.row.col.f32.bf16.bf16.f32 "
        "{%0,%1,%2,%3}, {%4,%5,%6,%7}, {%8,%9}, {%0,%1,%2,%3};"
        : "+f"(c[0]), "+f"(c[1]), "+f"(c[2]), "+f"(c[3])
        : "r"(a[0]), "r"(a[1]), "r"(a[2]), "r"(a[3]), "r"(b[0]), "r"(b[1]));
}

__device__ __forceinline__ unsigned packbf(float a, float b, float& ra, float& rb) {
    __nv_bfloat16 ha = __float2bfloat16_rn(a);
    __nv_bfloat16 hb = __float2bfloat16_rn(b);
    ra = a - __bfloat162float(ha);
    rb = b - __bfloat162float(hb);
    return (unsigned)__bfloat16_as_ushort(ha) |
           ((unsigned)__bfloat16_as_ushort(hb) << 16);
}
__device__ __forceinline__ unsigned packbf2(float a, float b) {
    __nv_bfloat16 ha = __float2bfloat16_rn(a);
    __nv_bfloat16 hb = __float2bfloat16_rn(b);
    return (unsigned)__bfloat16_as_ushort(ha) |
           ((unsigned)__bfloat16_as_ushort(hb) << 16);
}

// ---------------------------------------------------------------------------
// Split kernels.
// ---------------------------------------------------------------------------
__global__ void split_A(const float* __restrict__ x, int n4)  // layer 0 only
{
    int i = blockIdx.x * blockDim.x + threadIdx.x;
    if (i < n4) {
        float4 v = ((const float4*)x)[i];
        float rx, ry, rz, rw;
        uint2 h, l;
        h.x = packbf(v.x, v.y, rx, ry);
        h.y = packbf(v.z, v.w, rz, rw);
        l.x = packbf2(rx, ry);
        l.y = packbf2(rz, rw);
        ((uint2*)g_seqHi)[i] = h;
        ((uint2*)g_seqLo)[i] = l;
    }
}
__global__ void split_W(const float* __restrict__ W, int n4)
{
    int i = blockIdx.x * blockDim.x + threadIdx.x;
    if (i < n4) {
        float4 v = ((const float4*)W)[i];
        float rx, ry, rz, rw;
        uint2 h, l;
        h.x = packbf(v.x, v.y, rx, ry);
        h.y = packbf(v.z, v.w, rz, rw);
        l.x = packbf2(rx, ry);
        l.y = packbf2(rz, rw);
        ((uint2*)g_Whi)[i] = h;
        ((uint2*)g_Wlo)[i] = l;
    }
}

// ---------------------------------------------------------------------------
// Projection GEMM via bf16 m16n8k16 mma.sync (validated R12 kernel; A read
// directly from g_seqHi/Lo -- the persistent kernel writes next layer's input).
// ---------------------------------------------------------------------------
#define RS 10   // smem row stride (words)

__global__ __launch_bounds__(256) void gemm_bf(int K,
    const float* __restrict__ bi, const float* __restrict__ bh)
{
    __shared__ __align__(16) unsigned As[2 * 2 * 128 * RS];
    __shared__ __align__(16) unsigned Ws[2 * 2 * 64 * RS];

    const int tid = threadIdx.x;
    const int lane = tid & 31, wid = tid >> 5;
    const int wm = wid & 3, wn = wid >> 2;
    const int m0 = blockIdx.y << 7, n0 = blockIdx.x << 6;
    const int Kw = K >> 1;

    const int arow = tid >> 1, akq = (tid & 1) * 8;
    const int wrow = tid >> 2, wkq = (tid & 3) * 4;
    const unsigned* pA[2] = { g_seqHi + (size_t)(m0 + arow) * Kw + akq,
                              g_seqLo + (size_t)(m0 + arow) * Kw + akq };
    const unsigned* pW[2] = { g_Whi + (size_t)(n0 + wrow) * Kw + wkq,
                              g_Wlo + (size_t)(n0 + wrow) * Kw + wkq };

    float acc[2][4][4];
#pragma unroll
    for (int mt = 0; mt < 2; mt++)
#pragma unroll
        for (int nt = 0; nt < 4; nt++)
#pragma unroll
            for (int q = 0; q < 4; q++) acc[mt][nt][q] = 0.f;

    uint4 pa[2][2], pw[2];
#pragma unroll
    for (int sp = 0; sp < 2; sp++) {
        pa[sp][0] = *(const uint4*)(pA[sp]);
        pa[sp][1] = *(const uint4*)(pA[sp] + 4);
        pw[sp]    = *(const uint4*)(pW[sp]);
    }

    const int nch = K >> 5;
    for (int ch = 0; ch < nch; ch++) {
        __syncthreads();
#pragma unroll
        for (int sp = 0; sp < 2; sp++) {
#pragma unroll
            for (int f = 0; f < 2; f++) {
                const int kb = akq + f * 4;
                const int kc = kb >> 3, podd = (kb & 4) ? 1 : 0;
                unsigned* dst = &As[((sp * 2 + kc) * 128 + arow) * RS + podd];
                const unsigned* v = (const unsigned*)&pa[sp][f];
                dst[0] = v[0]; dst[2] = v[1]; dst[4] = v[2]; dst[6] = v[3];
            }
            {
                const int kc = wkq >> 3, podd = (wkq & 4) ? 1 : 0;
                unsigned* dst = &Ws[((sp * 2 + kc) * 64 + wrow) * RS + podd];
                const unsigned* v = (const unsigned*)&pw[sp];
                dst[0] = v[0]; dst[2] = v[1]; dst[4] = v[2]; dst[6] = v[3];
            }
        }
        __syncthreads();
        if (ch + 1 < nch) {
#pragma unroll
            for (int sp = 0; sp < 2; sp++) {
                pa[sp][0] = *(const uint4*)(pA[sp] + (ch + 1) * 16);
                pa[sp][1] = *(const uint4*)(pA[sp] + (ch + 1) * 16 + 4);
                pw[sp]    = *(const uint4*)(pW[sp] + (ch + 1) * 16);
            }
        }
#pragma unroll
        for (int kc = 0; kc < 2; kc++) {
            uint32_t af[2][2][4];
            uint32_t bf[2][4][2];
            const int co = 2 * (lane & 3);
#pragma unroll
            for (int sp = 0; sp < 2; sp++) {
#pragma unroll
                for (int mt = 0; mt < 2; mt++) {
                    const int mr = wm * 32 + mt * 16 + (lane >> 2);
                    uint2 lo = *(const uint2*)&As[((sp * 2 + kc) * 128 + mr) * RS + co];
                    uint2 hi = *(const uint2*)&As[((sp * 2 + kc) * 128 + mr + 8) * RS + co];
                    af[sp][mt][0] = lo.x;
                    af[sp][mt][2] = lo.y;
                    af[sp][mt][1] = hi.x;
                    af[sp][mt][3] = hi.y;
                }
#pragma unroll
                for (int nt = 0; nt < 4; nt++) {
                    const int nr = wn * 32 + nt * 8 + (lane >> 2);
                    uint2 bv = *(const uint2*)&Ws[((sp * 2 + kc) * 64 + nr) * RS + co];
                    bf[sp][nt][0] = bv.x;
                    bf[sp][nt][1] = bv.y;
                }
            }
#pragma unroll
            for (int mt = 0; mt < 2; mt++)
#pragma unroll
                for (int nt = 0; nt < 4; nt++) {
                    mma_bf16(acc[mt][nt], af[0][mt], bf[0][nt]);
                    mma_bf16(acc[mt][nt], af[0][mt], bf[1][nt]);
                    mma_bf16(acc[mt][nt], af[1][mt], bf[0][nt]);
                }
        }
    }

#pragma unroll
    for (int mt = 0; mt < 2; mt++) {
        const int m = m0 + wm * 32 + mt * 16 + (lane >> 2);
#pragma unroll
        for (int nt = 0; nt < 4; nt++) {
            const int n = n0 + wn * 32 + nt * 8 + 2 * (lane & 3);
            const float b0 = __ldg(&bi[n]) + __ldg(&bh[n]);
            const float b1 = __ldg(&bi[n + 1]) + __ldg(&bh[n + 1]);
            float2 o0 = make_float2(acc[mt][nt][0] + b0, acc[mt][nt][1] + b1);
            float2 o1 = make_float2(acc[mt][nt][2] + b0, acc[mt][nt][3] + b1);
            *(float2*)(g_xp + (size_t)m * FH + n)       = o0;
            *(float2*)(g_xp + (size_t)(m + 8) * FH + n) = o1;
        }
    }
}

__global__ void init_state()
{
    int i = blockIdx.x * blockDim.x + threadIdx.x;
    if (i == 0) g_bar = 0u;
    if (i < 32768) { g_shHi[i] = 0u; g_shLo[i] = 0u; }   // zero step-buffer 0
}

// ---------------------------------------------------------------------------
// Persistent HMMA recurrence. 128 blocks x 256 threads, 1 block/SM.
// Block owns h-cols j0..j0+7 => 32 gate rows. W slice split to bf16 hi/lo in
// SMEM once per layer (rows stride 520 words == 8 mod 32: conflict-free
// LDS.64 b-frags). h travels between steps as bf16 hi/lo global buffers;
// chunks staged in SMEM [kc][64][8] (stride 8: phase-conflict-free a-frags).
// 8 warps = 4m x 2n; per step 3072 mma. c state in registers; gates exchanged
// through a small Gs SMEM tile. h written to step buffer + sequence arrays
// (the latter = next layer's GEMM input, so split_A vanishes for layers 1,2).
// ---------------------------------------------------------------------------
#define WST 520
#define PSMEM ((2 * 32 * WST + 8192 + 2176) * 4)

__global__ __launch_bounds__(256, 1) void lstm_persist(const float* __restrict__ Whh)
{
    extern __shared__ unsigned su[];
    unsigned* WsH = su;
    unsigned* WsL = su + 32 * WST;
    unsigned* Hsm = su + 2 * 32 * WST;                 // [2buf][2sp][4kc][64][8]
    float* Gs = (float*)(su + 2 * 32 * WST + 8192);    // [64][34]

    const int tid = threadIdx.x;
    const int lane = tid & 31, wid = tid >> 5;
    const int wm = wid & 3, wn = wid >> 2;
    const int j0 = blockIdx.x << 3;

    // --- one-time W slice load + bf16 split + k8-permuted SMEM store ---
    {
        const int lw = tid >> 3;                       // local gate row 0..31
        const int ke = (tid & 7) * 128;
        const float* wp = Whh + (size_t)((lw >> 3) * Hh + j0 + (lw & 7)) * Hh + ke;
#pragma unroll 4
        for (int i = 0; i < 32; i++) {
            float4 v = *(const float4*)(wp + i * 4);
            float rx, ry, rz, rw;
            unsigned h0 = packbf(v.x, v.y, rx, ry);
            unsigned h1 = packbf(v.z, v.w, rz, rw);
            unsigned l0 = packbf2(rx, ry);
            unsigned l1 = packbf2(rz, rw);
            const int w0 = (ke + i * 4) >> 1;
            const int k16 = w0 >> 3;
            const int wc0 = w0 & 7;                    // even
            const int p0 = (wc0 < 4) ? 2 * wc0 : 2 * wc0 - 7;
            const int p1 = (wc0 + 1 < 4) ? 2 * wc0 + 2 : 2 * wc0 - 5;
            unsigned* dh = WsH + lw * WST + k16 * 8;
            unsigned* dl = WsL + lw * WST + k16 * 8;
            dh[p0] = h0; dh[p1] = h1;
            dl[p0] = l0; dl[p1] = l1;
        }
    }
    __syncthreads();

    const int fr = tid >> 2, fj = tid & 3;             // h-fill map
    const int mr = wm * 16 + (lane >> 2);
    const int co = 2 * (lane & 3);
    const int e0 = tid * 2;
    const int jj = e0 >> 6;                            // elementwise col
    const int eb = e0 & 63;                            // elementwise batch (even)

    float c_state[2] = {0.f, 0.f};

    for (int t = 0; t < Tt; t++) {
        const unsigned* rdH = g_shHi + (t & 1) * 32768;
        const unsigned* rdL = g_shLo + (t & 1) * 32768;

        // xp prefetch for the elementwise phase
        float xpv[2][4];
#pragma unroll
        for (int p = 0; p < 2; p++) {
            const float* xq = g_xp + ((size_t)(eb + p) * Tt + t) * FH + j0 + jj;
#pragma unroll
            for (int g = 0; g < 4; g++) xpv[p][g] = xq[g * Hh];
        }

        float cA[2][4], cB[2][4], cC[2][4];
#pragma unroll
        for (int nt = 0; nt < 2; nt++)
#pragma unroll
            for (int q = 0; q < 4; q++) { cA[nt][q] = 0.f; cB[nt][q] = 0.f; cC[nt][q] = 0.f; }

        uint4 pre[2][2];
        {
            const unsigned* ph = rdH + fr * 512 + fj * 4;
            const unsigned* pl = rdL + fr * 512 + fj * 4;
            pre[0][0] = __ldcg((const uint4*)(ph));
            pre[0][1] = __ldcg((const uint4*)(ph + 16));
            pre[1][0] = __ldcg((const uint4*)(pl));
            pre[1][1] = __ldcg((const uint4*)(pl + 16));
        }

        for (int ch = 0; ch < 16; ch++) {
            const int hb = ch & 1;
            __syncthreads();
#pragma unroll
            for (int sp = 0; sp < 2; sp++)
#pragma unroll
                for (int q = 0; q < 2; q++) {
                    const int jq = fj + 4 * q;
                    const int kc = jq >> 1, podd = jq & 1;
                    unsigned* dst = Hsm + (((hb * 2 + sp) * 4 + kc) * 64 + fr) * 8 + podd;
                    uint4 v = pre[sp][q];
                    dst[0] = v.x; dst[2] = v.y; dst[4] = v.z; dst[6] = v.w;
                }
            __syncthreads();
            if (ch + 1 < 16) {
                const unsigned* ph = rdH + fr * 512 + (ch + 1) * 32 + fj * 4;
                const unsigned* pl = rdL + fr * 512 + (ch + 1) * 32 + fj * 4;
                pre[0][0] = __ldcg((const uint4*)(ph));
                pre[0][1] = __ldcg((const uint4*)(ph + 16));
                pre[1][0] = __ldcg((const uint4*)(pl));
                pre[1][1] = __ldcg((const uint4*)(pl + 16));
            }
#pragma unroll
            for (int kc = 0; kc < 4; kc++) {
                const int ks = ch * 4 + kc;
                uint32_t aH[4], aL[4];
                {
                    const unsigned* ab = Hsm + ((hb * 2 + 0) * 4 + kc) * 512;
                    uint2 lo = *(const uint2*)(ab + mr * 8 + co);
                    uint2 hi = *(const uint2*)(ab + (mr + 8) * 8 + co);
                    aH[0] = lo.x; aH[2] = lo.y; aH[1] = hi.x; aH[3] = hi.y;
                    const unsigned* ab2 = Hsm + ((hb * 2 + 1) * 4 + kc) * 512;
                    uint2 lo2 = *(const uint2*)(ab2 + mr * 8 + co);
                    uint2 hi2 = *(const uint2*)(ab2 + (mr + 8) * 8 + co);
                    aL[0] = lo2.x; aL[2] = lo2.y; aL[1] = hi2.x; aL[3] = hi2.y;
                }
#pragma unroll
                for (int nt = 0; nt < 2; nt++) {
                    const int n = wn * 16 + nt * 8 + (lane >> 2);
                    uint2 bH = *(const uint2*)(WsH + n * WST + ks * 8 + co);
                    uint2 bL = *(const uint2*)(WsL + n * WST + ks * 8 + co);
                    uint32_t bh2[2] = {bH.x, bH.y};
                    uint32_t bl2[2] = {bL.x, bL.y};
                    mma_bf16(cA[nt], aH, bh2);
                    mma_bf16(cB[nt], aH, bl2);
                    mma_bf16(cC[nt], aL, bh2);
                }
            }
        }

        // C fragments -> Gs[batch][gate-row]
#pragma unroll
        for (int nt = 0; nt < 2; nt++) {
            const int n = wn * 16 + nt * 8 + co;
            const int m = wm * 16 + (lane >> 2);
            float s0 = cA[nt][0] + (cB[nt][0] + cC[nt][0]);
            float s1 = cA[nt][1] + (cB[nt][1] + cC[nt][1]);
            float s2 = cA[nt][2] + (cB[nt][2] + cC[nt][2]);
            float s3 = cA[nt][3] + (cB[nt][3] + cC[nt][3]);
            *(float2*)&Gs[m * 34 + n]       = make_float2(s0, s1);
            *(float2*)&Gs[(m + 8) * 34 + n] = make_float2(s2, s3);
        }
        __syncthreads();

        // Elementwise LSTM update; c in registers.
        unsigned short* wHs = (unsigned short*)g_shHi + ((t & 1) ^ 1) * 65536;
        unsigned short* wLs = (unsigned short*)g_shLo + ((t & 1) ^ 1) * 65536;
        unsigned short* sqH = (unsigned short*)g_seqHi;
        unsigned short* sqL = (unsigned short*)g_seqLo;
#pragma unroll
        for (int p = 0; p < 2; p++) {
            const int b = eb + p;
            float gi = Gs[b * 34 + jj]      + xpv[p][0];
            float gf = Gs[b * 34 + 8 + jj]  + xpv[p][1];
            float gg = Gs[b * 34 + 16 + jj] + xpv[p][2];
            float go = Gs[b * 34 + 24 + jj] + xpv[p][3];
            float si = 1.f / (1.f + expf(-gi));
            float sf = 1.f / (1.f + expf(-gf));
            float so = 1.f / (1.f + expf(-go));
            float cn = sf * c_state[p] + si * tanhf(gg);
            c_state[p] = cn;
            float hv = so * tanhf(cn);
            __nv_bfloat16 hh = __float2bfloat16_rn(hv);
            __nv_bfloat16 hl = __float2bfloat16_rn(hv - __bfloat162float(hh));
            const int ji = j0 + jj;
            wHs[b * 1024 + ji] = __bfloat16_as_ushort(hh);
            wLs[b * 1024 + ji] = __bfloat16_as_ushort(hl);
            const size_t sidx = ((size_t)b * Tt + t) * 1024 + ji;
            sqH[sidx] = __bfloat16_as_ushort(hh);
            sqL[sidx] = __bfloat16_as_ushort(hl);
        }

        // Grid barrier: monotonic counter, all 128 blocks resident.
        __threadfence();
        __syncthreads();
        if (tid == 0) {
            atomicAdd(&g_bar, 1u);
            const unsigned target = 128u * (unsigned)(t + 1);
            while (*(volatile unsigned*)&g_bar < target) { }
        }
        __syncthreads();
    }
}

__global__ void fc_kernel(const float* __restrict__ fw, const float* __restrict__ fb,
                          float* __restrict__ out)
{
    __shared__ float red[256];
    int b = blockIdx.x, tid = threadIdx.x;
    const unsigned short* sqH = (const unsigned short*)g_seqHi;
    const unsigned short* sqL = (const unsigned short*)g_seqLo;
    const size_t base = ((size_t)b * Tt + (Tt - 1)) * 1024;
    float s = 0.f;
    for (int j = tid; j < Hh; j += 256) {
        float hv = __bfloat162float(__ushort_as_bfloat16(sqH[base + j]))
                 + __bfloat162float(__ushort_as_bfloat16(sqL[base + j]));
        s += hv * fw[j];
    }
    red[tid] = s;
    __syncthreads();
    for (int o = 128; o > 0; o >>= 1) {
        if (tid < o) red[tid] += red[tid + o];
        __syncthreads();
    }
    if (tid == 0) out[b] = red[0] + fb[0];
}

extern "C" void kernel_launch(void* const* d_in, const int* in_sizes, int n_in,
                              void* d_out, int out_size)
{
    const float* x      = (const float*)d_in[0];
    const float* Wih[3] = {(const float*)d_in[1], (const float*)d_in[2], (const float*)d_in[3]};
    const float* Whh    = (const float*)d_in[4];   // [3][4096][1024]
    const float* bih    = (const float*)d_in[5];   // [3][4096]
    const float* bhh    = (const float*)d_in[6];   // [3][4096]
    const float* fcw    = (const float*)d_in[7];   // [1][1024]
    const float* fcb    = (const float*)d_in[8];   // [1]
    float* out = (float*)d_out;

    cudaFuncSetAttribute(lstm_persist,
                         cudaFuncAttributeMaxDynamicSharedMemorySize, PSMEM);

    for (int l = 0; l < 3; l++) {
        const int K = l ? Hh : 128;
        if (l == 0) {
            const int nA4 = Mm * 128 / 4;
            split_A<<<(nA4 + 255) / 256, 256>>>(x, nA4);
        }
        const int nW4 = FH * K / 4;
        split_W<<<(nW4 + 255) / 256, 256>>>(Wih[l], nW4);
        gemm_bf<<<dim3(64, 256), 256>>>(K, bih + l * FH, bhh + l * FH);
        init_state<<<32, 1024>>>();
        lstm_persist<<<128, 256, PSMEM>>>(Whh + (size_t)l * FH * Hh);
    }
    fc_kernel<<<64, 256>>>(fcw, fcb, out);
}

// round 15
// speedup vs baseline: 1.7985x; 1.0159x over previous
#include <cuda_runtime.h>
#include <cuda_bf16.h>
#include <math.h>
#include <stdint.h>
#include <stddef.h>

#define Hh 1024
#define FH 4096
#define Bb 64
#define Tt 512
#define Mm 32768   // B*T

// Scratch (device globals: no runtime allocation).
__device__ float g_xp[(size_t)Mm * FH];             // gate preactivations
__device__ unsigned g_seqHi[(size_t)Mm * Hh / 2];   // bf16 hidden seq (hi), word-packed
__device__ unsigned g_seqLo[(size_t)Mm * Hh / 2];   // bf16 hidden seq (lo)
__device__ unsigned g_Whi[(size_t)FH * Hh / 2];     // bf16-pair split of W_ih (hi)
__device__ unsigned g_Wlo[(size_t)FH * Hh / 2];     // bf16-pair split of W_ih (lo)
__device__ unsigned g_shHi[2 * 32768];              // per-step h (hi), 2 buffers
__device__ unsigned g_shLo[2 * 32768];              // per-step h (lo)
__device__ unsigned g_bar;                          // grid-barrier counter

// bf16 m16n8k16 warp MMA (plain PTX ISA, compiles on compute_103):
__device__ __forceinline__ void mma_bf16(float* c, const uint32_t* a, const uint32_t* b) {
    asm volatile(
        "mma.sync.aligned.m16n8k16.row.col.f32.bf16.bf16.f32 "
        "{%0,%1,%2,%3}, {%4,%5,%6,%7}, {%8,%9}, {%0,%1,%2,%3};"
        : "+f"(c[0]), "+f"(c[1]), "+f"(c[2]), "+f"(c[3])
        : "r"(a[0]), "r"(a[1]), "r"(a[2]), "r"(a[3]), "r"(b[0]), "r"(b[1]));
}

__device__ __forceinline__ unsigned packbf(float a, float b, float& ra, float& rb) {
    __nv_bfloat16 ha = __float2bfloat16_rn(a);
    __nv_bfloat16 hb = __float2bfloat16_rn(b);
    ra = a - __bfloat162float(ha);
    rb = b - __bfloat162float(hb);
    return (unsigned)__bfloat16_as_ushort(ha) |
           ((unsigned)__bfloat16_as_ushort(hb) << 16);
}
__device__ __forceinline__ unsigned packbf2(float a, float b) {
    __nv_bfloat16 ha = __float2bfloat16_rn(a);
    __nv_bfloat16 hb = __float2bfloat16_rn(b);
    return (unsigned)__bfloat16_as_ushort(ha) |
           ((unsigned)__bfloat16_as_ushort(hb) << 16);
}

// ---------------------------------------------------------------------------
// Split kernels.
// ---------------------------------------------------------------------------
__global__ void split_A(const float* __restrict__ x, int n4)  // layer 0 only
{
    int i = blockIdx.x * blockDim.x + threadIdx.x;
    if (i < n4) {
        float4 v = ((const float4*)x)[i];
        float rx, ry, rz, rw;
        uint2 h, l;
        h.x = packbf(v.x, v.y, rx, ry);
        h.y = packbf(v.z, v.w, rz, rw);
        l.x = packbf2(rx, ry);
        l.y = packbf2(rz, rw);
        ((uint2*)g_seqHi)[i] = h;
        ((uint2*)g_seqLo)[i] = l;
    }
}
__global__ void split_W(const float* __restrict__ W, int n4)
{
    int i = blockIdx.x * blockDim.x + threadIdx.x;
    if (i < n4) {
        float4 v = ((const float4*)W)[i];
        float rx, ry, rz, rw;
        uint2 h, l;
        h.x = packbf(v.x, v.y, rx, ry);
        h.y = packbf(v.z, v.w, rz, rw);
        l.x = packbf2(rx, ry);
        l.y = packbf2(rz, rw);
        ((uint2*)g_Whi)[i] = h;
        ((uint2*)g_Wlo)[i] = l;
    }
}

// ---------------------------------------------------------------------------
// Projection GEMM via bf16 m16n8k16 mma.sync (validated R12/R14 kernel).
// ---------------------------------------------------------------------------
#define RS 10   // smem row stride (words)

__global__ __launch_bounds__(256) void gemm_bf(int K,
    const float* __restrict__ bi, const float* __restrict__ bh)
{
    __shared__ __align__(16) unsigned As[2 * 2 * 128 * RS];
    __shared__ __align__(16) unsigned Ws[2 * 2 * 64 * RS];

    const int tid = threadIdx.x;
    const int lane = tid & 31, wid = tid >> 5;
    const int wm = wid & 3, wn = wid >> 2;
    const int m0 = blockIdx.y << 7, n0 = blockIdx.x << 6;
    const int Kw = K >> 1;

    const int arow = tid >> 1, akq = (tid & 1) * 8;
    const int wrow = tid >> 2, wkq = (tid & 3) * 4;
    const unsigned* pA[2] = { g_seqHi + (size_t)(m0 + arow) * Kw + akq,
                              g_seqLo + (size_t)(m0 + arow) * Kw + akq };
    const unsigned* pW[2] = { g_Whi + (size_t)(n0 + wrow) * Kw + wkq,
                              g_Wlo + (size_t)(n0 + wrow) * Kw + wkq };

    float acc[2][4][4];
#pragma unroll
    for (int mt = 0; mt < 2; mt++)
#pragma unroll
        for (int nt = 0; nt < 4; nt++)
#pragma unroll
            for (int q = 0; q < 4; q++) acc[mt][nt][q] = 0.f;

    uint4 pa[2][2], pw[2];
#pragma unroll
    for (int sp = 0; sp < 2; sp++) {
        pa[sp][0] = *(const uint4*)(pA[sp]);
        pa[sp][1] = *(const uint4*)(pA[sp] + 4);
        pw[sp]    = *(const uint4*)(pW[sp]);
    }

    const int nch = K >> 5;
    for (int ch = 0; ch < nch; ch++) {
        __syncthreads();
#pragma unroll
        for (int sp = 0; sp < 2; sp++) {
#pragma unroll
            for (int f = 0; f < 2; f++) {
                const int kb = akq + f * 4;
                const int kc = kb >> 3, podd = (kb & 4) ? 1 : 0;
                unsigned* dst = &As[((sp * 2 + kc) * 128 + arow) * RS + podd];
                const unsigned* v = (const unsigned*)&pa[sp][f];
                dst[0] = v[0]; dst[2] = v[1]; dst[4] = v[2]; dst[6] = v[3];
            }
            {
                const int kc = wkq >> 3, podd = (wkq & 4) ? 1 : 0;
                unsigned* dst = &Ws[((sp * 2 + kc) * 64 + wrow) * RS + podd];
                const unsigned* v = (const unsigned*)&pw[sp];
                dst[0] = v[0]; dst[2] = v[1]; dst[4] = v[2]; dst[6] = v[3];
            }
        }
        __syncthreads();
        if (ch + 1 < nch) {
#pragma unroll
            for (int sp = 0; sp < 2; sp++) {
                pa[sp][0] = *(const uint4*)(pA[sp] + (ch + 1) * 16);
                pa[sp][1] = *(const uint4*)(pA[sp] + (ch + 1) * 16 + 4);
                pw[sp]    = *(const uint4*)(pW[sp] + (ch + 1) * 16);
            }
        }
#pragma unroll
        for (int kc = 0; kc < 2; kc++) {
            uint32_t af[2][2][4];
            uint32_t bf[2][4][2];
            const int co = 2 * (lane & 3);
#pragma unroll
            for (int sp = 0; sp < 2; sp++) {
#pragma unroll
                for (int mt = 0; mt < 2; mt++) {
                    const int mr = wm * 32 + mt * 16 + (lane >> 2);
                    uint2 lo = *(const uint2*)&As[((sp * 2 + kc) * 128 + mr) * RS + co];
                    uint2 hi = *(const uint2*)&As[((sp * 2 + kc) * 128 + mr + 8) * RS + co];
                    af[sp][mt][0] = lo.x;
                    af[sp][mt][2] = lo.y;
                    af[sp][mt][1] = hi.x;
                    af[sp][mt][3] = hi.y;
                }
#pragma unroll
                for (int nt = 0; nt < 4; nt++) {
                    const int nr = wn * 32 + nt * 8 + (lane >> 2);
                    uint2 bv = *(const uint2*)&Ws[((sp * 2 + kc) * 64 + nr) * RS + co];
                    bf[sp][nt][0] = bv.x;
                    bf[sp][nt][1] = bv.y;
                }
            }
#pragma unroll
            for (int mt = 0; mt < 2; mt++)
#pragma unroll
                for (int nt = 0; nt < 4; nt++) {
                    mma_bf16(acc[mt][nt], af[0][mt], bf[0][nt]);
                    mma_bf16(acc[mt][nt], af[0][mt], bf[1][nt]);
                    mma_bf16(acc[mt][nt], af[1][mt], bf[0][nt]);
                }
        }
    }

#pragma unroll
    for (int mt = 0; mt < 2; mt++) {
        const int m = m0 + wm * 32 + mt * 16 + (lane >> 2);
#pragma unroll
        for (int nt = 0; nt < 4; nt++) {
            const int n = n0 + wn * 32 + nt * 8 + 2 * (lane & 3);
            const float b0 = __ldg(&bi[n]) + __ldg(&bh[n]);
            const float b1 = __ldg(&bi[n + 1]) + __ldg(&bh[n + 1]);
            float2 o0 = make_float2(acc[mt][nt][0] + b0, acc[mt][nt][1] + b1);
            float2 o1 = make_float2(acc[mt][nt][2] + b0, acc[mt][nt][3] + b1);
            *(float2*)(g_xp + (size_t)m * FH + n)       = o0;
            *(float2*)(g_xp + (size_t)(m + 8) * FH + n) = o1;
        }
    }
}

__global__ void init_state()
{
    int i = blockIdx.x * blockDim.x + threadIdx.x;
    if (i == 0) g_bar = 0u;
    if (i < 32768) { g_shHi[i] = 0u; g_shLo[i] = 0u; }   // zero step-buffer 0
}

// ---------------------------------------------------------------------------
// Persistent HMMA recurrence, v2: warp tiles m32(batch) x n32(gates), K split
// into 4 quarters (warp = (group, batch-half)). Fragment redundancy halves
// vs R14 (a x1, b x2) -> crossbar/step ~4096 wf instead of 8192.
// Per round (8/step): stage 32 k-elements for ALL 4 quarters (8 buffers,
// one __syncthreads), each group computes its own slice. K-partials combined
// via 2-phase Gs (groups 0/2 store, sync, groups 1/3 add). c in registers.
// ---------------------------------------------------------------------------
#define WST 520
#define PSMEM ((2 * 32 * WST + 16384 + 2 * 64 * 34) * 4)

__global__ __launch_bounds__(256, 1) void lstm_persist(const float* __restrict__ Whh)
{
    extern __shared__ unsigned su[];
    unsigned* WsH = su;
    unsigned* WsL = su + 32 * WST;
    unsigned* Hsm = su + 2 * 32 * WST;                 // [4g][2buf][2sp][2kc][64][8]
    float* Gs = (float*)(su + 2 * 32 * WST + 16384);   // [2][64][34]

    const int tid = threadIdx.x;
    const int lane = tid & 31, wid = tid >> 5;
    const int grp = wid >> 1;                          // k-quarter 0..3
    const int pos = wid & 1;                           // batch half
    const int j0 = blockIdx.x << 3;

    // --- one-time W slice load + bf16 split + k8-permuted SMEM store ---
    {
        const int lw = tid >> 3;                       // local gate row 0..31
        const int ke = (tid & 7) * 128;
        const float* wp = Whh + (size_t)((lw >> 3) * Hh + j0 + (lw & 7)) * Hh + ke;
#pragma unroll 4
        for (int i = 0; i < 32; i++) {
            float4 v = *(const float4*)(wp + i * 4);
            float rx, ry, rz, rw;
            unsigned h0 = packbf(v.x, v.y, rx, ry);
            unsigned h1 = packbf(v.z, v.w, rz, rw);
            unsigned l0 = packbf2(rx, ry);
            unsigned l1 = packbf2(rz, rw);
            const int w0 = (ke + i * 4) >> 1;
            const int k16 = w0 >> 3;
            const int wc0 = w0 & 7;                    // even
            const int p0 = (wc0 < 4) ? 2 * wc0 : 2 * wc0 - 7;
            const int p1 = (wc0 + 1 < 4) ? 2 * wc0 + 2 : 2 * wc0 - 5;
            unsigned* dh = WsH + lw * WST + k16 * 8;
            unsigned* dl = WsL + lw * WST + k16 * 8;
            dh[p0] = h0; dh[p1] = h1;
            dl[p0] = l0; dl[p1] = l1;
        }
    }
    __syncthreads();

    const int fr = tid >> 2, fj = tid & 3;             // h-fill map
    const int kcF = fj >> 1, fodd = fj & 1;
    const int mrb = pos * 32 + (lane >> 2);            // batch-row base
    const int co = 2 * (lane & 3);
    const int e0 = tid * 2;
    const int jj = e0 >> 6;                            // elementwise col
    const int eb = e0 & 63;                            // elementwise batch (even)

    float c_state[2] = {0.f, 0.f};

    for (int t = 0; t < Tt; t++) {
        const unsigned* rdH = g_shHi + (t & 1) * 32768;
        const unsigned* rdL = g_shLo + (t & 1) * 32768;

        // xp prefetch (DRAM, hidden under first rounds)
        float xpv[2][4];
#pragma unroll
        for (int p = 0; p < 2; p++) {
            const float* xq = g_xp + ((size_t)(eb + p) * Tt + t) * FH + j0 + jj;
#pragma unroll
            for (int g = 0; g < 4; g++) xpv[p][g] = xq[g * Hh];
        }

        float cA[2][4][4], cB[2][4][4], cC[2][4][4];
#pragma unroll
        for (int mt = 0; mt < 2; mt++)
#pragma unroll
            for (int nt = 0; nt < 4; nt++)
#pragma unroll
                for (int q = 0; q < 4; q++) {
                    cA[mt][nt][q] = 0.f; cB[mt][nt][q] = 0.f; cC[mt][nt][q] = 0.f;
                }

        uint4 pre[4][2];
#pragma unroll
        for (int g = 0; g < 4; g++) {
            const int w0 = fr * 512 + g * 128 + fj * 4;
            pre[g][0] = __ldcg((const uint4*)(rdH + w0));
            pre[g][1] = __ldcg((const uint4*)(rdL + w0));
        }

        for (int r = 0; r < 8; r++) {
            const int buf = r & 1;
            // stage all 4 quarters' 32-k slices (permuted store)
#pragma unroll
            for (int g = 0; g < 4; g++)
#pragma unroll
                for (int sp = 0; sp < 2; sp++) {
                    unsigned* dst = Hsm
                        + ((((((g << 1) | buf) << 1) | sp) * 2 + kcF) * 64 + fr) * 8 + fodd;
                    uint4 v = pre[g][sp];
                    dst[0] = v.x; dst[2] = v.y; dst[4] = v.z; dst[6] = v.w;
                }
            __syncthreads();
            if (r < 7) {
#pragma unroll
                for (int g = 0; g < 4; g++) {
                    const int w0 = fr * 512 + g * 128 + (r + 1) * 16 + fj * 4;
                    pre[g][0] = __ldcg((const uint4*)(rdH + w0));
                    pre[g][1] = __ldcg((const uint4*)(rdL + w0));
                }
            }
            // compute this group's 32-k slice
#pragma unroll
            for (int kc = 0; kc < 2; kc++) {
                const int ks = grp * 16 + r * 2 + kc;
                uint32_t aH[2][4], aL[2][4];
                const unsigned* abH = Hsm + (((((grp << 1) | buf) << 1) | 0) * 2 + kc) * 512;
                const unsigned* abL = Hsm + (((((grp << 1) | buf) << 1) | 1) * 2 + kc) * 512;
#pragma unroll
                for (int mt = 0; mt < 2; mt++) {
                    const int mr = mrb + mt * 16;
                    uint2 lo = *(const uint2*)(abH + mr * 8 + co);
                    uint2 hi = *(const uint2*)(abH + (mr + 8) * 8 + co);
                    aH[mt][0] = lo.x; aH[mt][2] = lo.y; aH[mt][1] = hi.x; aH[mt][3] = hi.y;
                    uint2 lo2 = *(const uint2*)(abL + mr * 8 + co);
                    uint2 hi2 = *(const uint2*)(abL + (mr + 8) * 8 + co);
                    aL[mt][0] = lo2.x; aL[mt][2] = lo2.y; aL[mt][1] = hi2.x; aL[mt][3] = hi2.y;
                }
#pragma unroll
                for (int nt = 0; nt < 4; nt++) {
                    const int n = nt * 8 + (lane >> 2);
                    uint2 bH = *(const uint2*)(WsH + n * WST + ks * 8 + co);
                    uint2 bL = *(const uint2*)(WsL + n * WST + ks * 8 + co);
                    uint32_t bh2[2] = {bH.x, bH.y};
                    uint32_t bl2[2] = {bL.x, bL.y};
#pragma unroll
                    for (int mt = 0; mt < 2; mt++) {
                        mma_bf16(cA[mt][nt], aH[mt], bh2);
                        mma_bf16(cB[mt][nt], aH[mt], bl2);
                        mma_bf16(cC[mt][nt], aL[mt], bh2);
                    }
                }
            }
        }

        // ---- K-partial reduction into Gs: phase1 store (groups 0,2),
        //      phase2 add (groups 1,3). Gs half = grp>>1 (k 0-511 / 512-1023).
        float* gdst = Gs + (grp >> 1) * (64 * 34);
        if ((grp & 1) == 0) {
#pragma unroll
            for (int mt = 0; mt < 2; mt++) {
                const int m = mrb + mt * 16;
#pragma unroll
                for (int nt = 0; nt < 4; nt++) {
                    const int n = nt * 8 + co;
                    float s0 = cA[mt][nt][0] + cB[mt][nt][0] + cC[mt][nt][0];
                    float s1 = cA[mt][nt][1] + cB[mt][nt][1] + cC[mt][nt][1];
                    float s2 = cA[mt][nt][2] + cB[mt][nt][2] + cC[mt][nt][2];
                    float s3 = cA[mt][nt][3] + cB[mt][nt][3] + cC[mt][nt][3];
                    *(float2*)&gdst[m * 34 + n]       = make_float2(s0, s1);
                    *(float2*)&gdst[(m + 8) * 34 + n] = make_float2(s2, s3);
                }
            }
        }
        __syncthreads();
        if ((grp & 1) == 1) {
#pragma unroll
            for (int mt = 0; mt < 2; mt++) {
                const int m = mrb + mt * 16;
#pragma unroll
                for (int nt = 0; nt < 4; nt++) {
                    const int n = nt * 8 + co;
                    float s0 = cA[mt][nt][0] + cB[mt][nt][0] + cC[mt][nt][0];
                    float s1 = cA[mt][nt][1] + cB[mt][nt][1] + cC[mt][nt][1];
                    float s2 = cA[mt][nt][2] + cB[mt][nt][2] + cC[mt][nt][2];
                    float s3 = cA[mt][nt][3] + cB[mt][nt][3] + cC[mt][nt][3];
                    float2 v0 = *(float2*)&gdst[m * 34 + n];
                    float2 v1 = *(float2*)&gdst[(m + 8) * 34 + n];
                    v0.x += s0; v0.y += s1; v1.x += s2; v1.y += s3;
                    *(float2*)&gdst[m * 34 + n]       = v0;
                    *(float2*)&gdst[(m + 8) * 34 + n] = v1;
                }
            }
        }
        __syncthreads();

        // Elementwise LSTM update; c in registers.
        unsigned short* wHs = (unsigned short*)g_shHi + ((t & 1) ^ 1) * 65536;
        unsigned short* wLs = (unsigned short*)g_shLo + ((t & 1) ^ 1) * 65536;
        unsigned short* sqH = (unsigned short*)g_seqHi;
        unsigned short* sqL = (unsigned short*)g_seqLo;
        const float* Gs1 = Gs + 64 * 34;
#pragma unroll
        for (int p = 0; p < 2; p++) {
            const int b = eb + p;
            float gi = Gs[b * 34 + jj]      + Gs1[b * 34 + jj]      + xpv[p][0];
            float gf = Gs[b * 34 + 8 + jj]  + Gs1[b * 34 + 8 + jj]  + xpv[p][1];
            float gg = Gs[b * 34 + 16 + jj] + Gs1[b * 34 + 16 + jj] + xpv[p][2];
            float go = Gs[b * 34 + 24 + jj] + Gs1[b * 34 + 24 + jj] + xpv[p][3];
            float si = 1.f / (1.f + expf(-gi));
            float sf = 1.f / (1.f + expf(-gf));
            float so = 1.f / (1.f + expf(-go));
            float cn = sf * c_state[p] + si * tanhf(gg);
            c_state[p] = cn;
            float hv = so * tanhf(cn);
            __nv_bfloat16 hh = __float2bfloat16_rn(hv);
            __nv_bfloat16 hl = __float2bfloat16_rn(hv - __bfloat162float(hh));
            const int ji = j0 + jj;
            wHs[b * 1024 + ji] = __bfloat16_as_ushort(hh);
            wLs[b * 1024 + ji] = __bfloat16_as_ushort(hl);
            const size_t sidx = ((size_t)b * Tt + t) * 1024 + ji;
            sqH[sidx] = __bfloat16_as_ushort(hh);
            sqL[sidx] = __bfloat16_as_ushort(hl);
        }

        // Grid barrier: monotonic counter, all 128 blocks resident.
        __threadfence();
        __syncthreads();
        if (tid == 0) {
            atomicAdd(&g_bar, 1u);
            const unsigned target = 128u * (unsigned)(t + 1);
            while (*(volatile unsigned*)&g_bar < target) { }
        }
        __syncthreads();
    }
}

__global__ void fc_kernel(const float* __restrict__ fw, const float* __restrict__ fb,
                          float* __restrict__ out)
{
    __shared__ float red[256];
    int b = blockIdx.x, tid = threadIdx.x;
    const unsigned short* sqH = (const unsigned short*)g_seqHi;
    const unsigned short* sqL = (const unsigned short*)g_seqLo;
    const size_t base = ((size_t)b * Tt + (Tt - 1)) * 1024;
    float s = 0.f;
    for (int j = tid; j < Hh; j += 256) {
        float hv = __bfloat162float(__ushort_as_bfloat16(sqH[base + j]))
                 + __bfloat162float(__ushort_as_bfloat16(sqL[base + j]));
        s += hv * fw[j];
    }
    red[tid] = s;
    __syncthreads();
    for (int o = 128; o > 0; o >>= 1) {
        if (tid < o) red[tid] += red[tid + o];
        __syncthreads();
    }
    if (tid == 0) out[b] = red[0] + fb[0];
}

extern "C" void kernel_launch(void* const* d_in, const int* in_sizes, int n_in,
                              void* d_out, int out_size)
{
    const float* x      = (const float*)d_in[0];
    const float* Wih[3] = {(const float*)d_in[1], (const float*)d_in[2], (const float*)d_in[3]};
    const float* Whh    = (const float*)d_in[4];   // [3][4096][1024]
    const float* bih    = (const float*)d_in[5];   // [3][4096]
    const float* bhh    = (const float*)d_in[6];   // [3][4096]
    const float* fcw    = (const float*)d_in[7];   // [1][1024]
    const float* fcb    = (const float*)d_in[8];   // [1]
    float* out = (float*)d_out;

    cudaFuncSetAttribute(lstm_persist,
                         cudaFuncAttributeMaxDynamicSharedMemorySize, PSMEM);

    for (int l = 0; l < 3; l++) {
        const int K = l ? Hh : 128;
        if (l == 0) {
            const int nA4 = Mm * 128 / 4;
            split_A<<<(nA4 + 255) / 256, 256>>>(x, nA4);
        }
        const int nW4 = FH * K / 4;
        split_W<<<(nW4 + 255) / 256, 256>>>(Wih[l], nW4);
        gemm_bf<<<dim3(64, 256), 256>>>(K, bih + l * FH, bhh + l * FH);
        init_state<<<32, 1024>>>();
        lstm_persist<<<128, 256, PSMEM>>>(Whh + (size_t)l * FH * Hh);
    }
    fc_kernel<<<64, 256>>>(fcw, fcb, out);
}

// round 16
// speedup vs baseline: 2.3304x; 1.2957x over previous
#include <cuda_runtime.h>
#include <cuda_bf16.h>
#include <math.h>
#include <stdint.h>
#include <stddef.h>

#define Hh 1024
#define FH 4096
#define Bb 64
#define Tt 512
#define Mm 32768   // B*T

// Scratch (device globals: no runtime allocation).
__device__ float g_xp[(size_t)Mm * FH];             // gate preactivations
__device__ unsigned g_seqHi[(size_t)Mm * Hh / 2];   // bf16 hidden seq (hi), word-packed
__device__ unsigned g_seqLo[(size_t)Mm * Hh / 2];   // bf16 hidden seq (lo)
__device__ unsigned g_Whi[(size_t)FH * Hh / 2];     // bf16-pair split of W_ih (hi)
__device__ unsigned g_Wlo[(size_t)FH * Hh / 2];     // bf16-pair split of W_ih (lo)
__device__ unsigned g_shHi[2 * 32768];              // per-step h (hi), 2 buffers
__device__ unsigned g_shLo[2 * 32768];              // per-step h (lo)
__device__ unsigned g_bar;                          // grid-barrier counter

// bf16 m16n8k16 warp MMA (plain PTX ISA, compiles on compute_103):
__device__ __forceinline__ void mma_bf16(float* c, const uint32_t* a, const uint32_t* b) {
    asm volatile(
        "mma.sync.aligned.m16n8k16.row.col.f32.bf16.bf16.f32 "
        "{%0,%1,%2,%3}, {%4,%5,%6,%7}, {%8,%9}, {%0,%1,%2,%3};"
        : "+f"(c[0]), "+f"(c[1]), "+f"(c[2]), "+f"(c[3])
        : "r"(a[0]), "r"(a[1]), "r"(a[2]), "r"(a[3]), "r"(b[0]), "r"(b[1]));
}

__device__ __forceinline__ unsigned packbf(float a, float b, float& ra, float& rb) {
    __nv_bfloat16 ha = __float2bfloat16_rn(a);
    __nv_bfloat16 hb = __float2bfloat16_rn(b);
    ra = a - __bfloat162float(ha);
    rb = b - __bfloat162float(hb);
    return (unsigned)__bfloat16_as_ushort(ha) |
           ((unsigned)__bfloat16_as_ushort(hb) << 16);
}
__device__ __forceinline__ unsigned packbf2(float a, float b) {
    __nv_bfloat16 ha = __float2bfloat16_rn(a);
    __nv_bfloat16 hb = __float2bfloat16_rn(b);
    return (unsigned)__bfloat16_as_ushort(ha) |
           ((unsigned)__bfloat16_as_ushort(hb) << 16);
}

// ---------------------------------------------------------------------------
// Split kernels. split_W also does per-layer init (barrier reset + step-buf0
// zeroing) so no separate init launch exists -> lstm_persist lands at global
// launch index 3, where ncu profiles.
// ---------------------------------------------------------------------------
__global__ void split_A(const float* __restrict__ x, int n4)  // layer 0 only
{
    int i = blockIdx.x * blockDim.x + threadIdx.x;
    if (i < n4) {
        float4 v = ((const float4*)x)[i];
        float rx, ry, rz, rw;
        uint2 h, l;
        h.x = packbf(v.x, v.y, rx, ry);
        h.y = packbf(v.z, v.w, rz, rw);
        l.x = packbf2(rx, ry);
        l.y = packbf2(rz, rw);
        ((uint2*)g_seqHi)[i] = h;
        ((uint2*)g_seqLo)[i] = l;
    }
}
__global__ void split_W(const float* __restrict__ W, int n4)
{
    int i = blockIdx.x * blockDim.x + threadIdx.x;
    if (i == 0) g_bar = 0u;
    if (i < 32768) { g_shHi[i] = 0u; g_shLo[i] = 0u; }   // zero step-buffer 0
    if (i < n4) {
        float4 v = ((const float4*)W)[i];
        float rx, ry, rz, rw;
        uint2 h, l;
        h.x = packbf(v.x, v.y, rx, ry);
        h.y = packbf(v.z, v.w, rz, rw);
        l.x = packbf2(rx, ry);
        l.y = packbf2(rz, rw);
        ((uint2*)g_Whi)[i] = h;
        ((uint2*)g_Wlo)[i] = l;
    }
}

// ---------------------------------------------------------------------------
// Projection GEMM via bf16 m16n8k16 mma.sync (validated R12/R14 kernel).
// ---------------------------------------------------------------------------
#define RS 10   // smem row stride (words)

__global__ __launch_bounds__(256) void gemm_bf(int K,
    const float* __restrict__ bi, const float* __restrict__ bh)
{
    __shared__ __align__(16) unsigned As[2 * 2 * 128 * RS];
    __shared__ __align__(16) unsigned Ws[2 * 2 * 64 * RS];

    const int tid = threadIdx.x;
    const int lane = tid & 31, wid = tid >> 5;
    const int wm = wid & 3, wn = wid >> 2;
    const int m0 = blockIdx.y << 7, n0 = blockIdx.x << 6;
    const int Kw = K >> 1;

    const int arow = tid >> 1, akq = (tid & 1) * 8;
    const int wrow = tid >> 2, wkq = (tid & 3) * 4;
    const unsigned* pA[2] = { g_seqHi + (size_t)(m0 + arow) * Kw + akq,
                              g_seqLo + (size_t)(m0 + arow) * Kw + akq };
    const unsigned* pW[2] = { g_Whi + (size_t)(n0 + wrow) * Kw + wkq,
                              g_Wlo + (size_t)(n0 + wrow) * Kw + wkq };

    float acc[2][4][4];
#pragma unroll
    for (int mt = 0; mt < 2; mt++)
#pragma unroll
        for (int nt = 0; nt < 4; nt++)
#pragma unroll
            for (int q = 0; q < 4; q++) acc[mt][nt][q] = 0.f;

    uint4 pa[2][2], pw[2];
#pragma unroll
    for (int sp = 0; sp < 2; sp++) {
        pa[sp][0] = *(const uint4*)(pA[sp]);
        pa[sp][1] = *(const uint4*)(pA[sp] + 4);
        pw[sp]    = *(const uint4*)(pW[sp]);
    }

    const int nch = K >> 5;
    for (int ch = 0; ch < nch; ch++) {
        __syncthreads();
#pragma unroll
        for (int sp = 0; sp < 2; sp++) {
#pragma unroll
            for (int f = 0; f < 2; f++) {
                const int kb = akq + f * 4;
                const int kc = kb >> 3, podd = (kb & 4) ? 1 : 0;
                unsigned* dst = &As[((sp * 2 + kc) * 128 + arow) * RS + podd];
                const unsigned* v = (const unsigned*)&pa[sp][f];
                dst[0] = v[0]; dst[2] = v[1]; dst[4] = v[2]; dst[6] = v[3];
            }
            {
                const int kc = wkq >> 3, podd = (wkq & 4) ? 1 : 0;
                unsigned* dst = &Ws[((sp * 2 + kc) * 64 + wrow) * RS + podd];
                const unsigned* v = (const unsigned*)&pw[sp];
                dst[0] = v[0]; dst[2] = v[1]; dst[4] = v[2]; dst[6] = v[3];
            }
        }
        __syncthreads();
        if (ch + 1 < nch) {
#pragma unroll
            for (int sp = 0; sp < 2; sp++) {
                pa[sp][0] = *(const uint4*)(pA[sp] + (ch + 1) * 16);
                pa[sp][1] = *(const uint4*)(pA[sp] + (ch + 1) * 16 + 4);
                pw[sp]    = *(const uint4*)(pW[sp] + (ch + 1) * 16);
            }
        }
#pragma unroll
        for (int kc = 0; kc < 2; kc++) {
            uint32_t af[2][2][4];
            uint32_t bf[2][4][2];
            const int co = 2 * (lane & 3);
#pragma unroll
            for (int sp = 0; sp < 2; sp++) {
#pragma unroll
                for (int mt = 0; mt < 2; mt++) {
                    const int mr = wm * 32 + mt * 16 + (lane >> 2);
                    uint2 lo = *(const uint2*)&As[((sp * 2 + kc) * 128 + mr) * RS + co];
                    uint2 hi = *(const uint2*)&As[((sp * 2 + kc) * 128 + mr + 8) * RS + co];
                    af[sp][mt][0] = lo.x;
                    af[sp][mt][2] = lo.y;
                    af[sp][mt][1] = hi.x;
                    af[sp][mt][3] = hi.y;
                }
#pragma unroll
                for (int nt = 0; nt < 4; nt++) {
                    const int nr = wn * 32 + nt * 8 + (lane >> 2);
                    uint2 bv = *(const uint2*)&Ws[((sp * 2 + kc) * 64 + nr) * RS + co];
                    bf[sp][nt][0] = bv.x;
                    bf[sp][nt][1] = bv.y;
                }
            }
#pragma unroll
            for (int mt = 0; mt < 2; mt++)
#pragma unroll
                for (int nt = 0; nt < 4; nt++) {
                    mma_bf16(acc[mt][nt], af[0][mt], bf[0][nt]);
                    mma_bf16(acc[mt][nt], af[0][mt], bf[1][nt]);
                    mma_bf16(acc[mt][nt], af[1][mt], bf[0][nt]);
                }
        }
    }

#pragma unroll
    for (int mt = 0; mt < 2; mt++) {
        const int m = m0 + wm * 32 + mt * 16 + (lane >> 2);
#pragma unroll
        for (int nt = 0; nt < 4; nt++) {
            const int n = n0 + wn * 32 + nt * 8 + 2 * (lane & 3);
            const float b0 = __ldg(&bi[n]) + __ldg(&bh[n]);
            const float b1 = __ldg(&bi[n + 1]) + __ldg(&bh[n + 1]);
            float2 o0 = make_float2(acc[mt][nt][0] + b0, acc[mt][nt][1] + b1);
            float2 o1 = make_float2(acc[mt][nt][2] + b0, acc[mt][nt][3] + b1);
            *(float2*)(g_xp + (size_t)m * FH + n)       = o0;
            *(float2*)(g_xp + (size_t)(m + 8) * FH + n) = o1;
        }
    }
}

// ---------------------------------------------------------------------------
// Persistent HMMA recurrence, v3. Same warp decomposition as v2 (4 k-quarter
// groups x 2 batch halves, warp m32 x n32), but:
//  - Hsm row stride 10, kc stride 656 (==16 mod 32): staging STS now hits 32
//    distinct banks (was 4-way conflicted at stride 8) -> ~6k wf/step saved.
//  - Gs gate-exchange buffer ALIASED onto buf0 staging regions (free after
//    round 6; round-7 reads only buf1 regions; next-step reuse is behind the
//    grid barrier) -> pays the padding SMEM cost.
//  - Elementwise remapped (jj=tid&7, b=tid>>3) for coalesced h/xp/Gs access.
//  - xp(t+1) prefetched before the grid barrier (h-independent).
// ---------------------------------------------------------------------------
#define WST 520
#define HKC 656                       // Hsm kc stride (words), ==16 mod 32
#define HSP (2 * HKC)                 // per-sp block
#define HRG (2 * HSP)                 // per-(g,buf) region = 2624 words
#define HSM_WORDS (8 * HRG)           // 20992 words
#define PSMEM ((2 * 32 * WST + HSM_WORDS) * 4)

__global__ __launch_bounds__(256, 1) void lstm_persist(const float* __restrict__ Whh)
{
    extern __shared__ unsigned su[];
    unsigned* WsH = su;
    unsigned* WsL = su + 32 * WST;
    unsigned* Hsm = su + 2 * 32 * WST;   // [g*2+buf][sp][kc-656][64][10]
    float* Gs0 = (float*)(Hsm);          // alias: region (g0,buf0)
    float* Gs1 = (float*)(Hsm + 2 * HRG);// alias: region (g1,buf0)

    const int tid = threadIdx.x;
    const int lane = tid & 31, wid = tid >> 5;
    const int grp = wid >> 1;                          // k-quarter 0..3
    const int pos = wid & 1;                           // batch half
    const int j0 = blockIdx.x << 3;

    // --- one-time W slice load + bf16 split + k8-permuted SMEM store ---
    {
        const int lw = tid >> 3;                       // local gate row 0..31
        const int ke = (tid & 7) * 128;
        const float* wp = Whh + (size_t)((lw >> 3) * Hh + j0 + (lw & 7)) * Hh + ke;
#pragma unroll 4
        for (int i = 0; i < 32; i++) {
            float4 v = *(const float4*)(wp + i * 4);
            float rx, ry, rz, rw;
            unsigned h0 = packbf(v.x, v.y, rx, ry);
            unsigned h1 = packbf(v.z, v.w, rz, rw);
            unsigned l0 = packbf2(rx, ry);
            unsigned l1 = packbf2(rz, rw);
            const int w0 = (ke + i * 4) >> 1;
            const int k16 = w0 >> 3;
            const int wc0 = w0 & 7;                    // even
            const int p0 = (wc0 < 4) ? 2 * wc0 : 2 * wc0 - 7;
            const int p1 = (wc0 + 1 < 4) ? 2 * wc0 + 2 : 2 * wc0 - 5;
            unsigned* dh = WsH + lw * WST + k16 * 8;
            unsigned* dl = WsL + lw * WST + k16 * 8;
            dh[p0] = h0; dh[p1] = h1;
            dl[p0] = l0; dl[p1] = l1;
        }
    }
    __syncthreads();

    const int fr = tid >> 2, fj = tid & 3;             // h-fill map
    const int kcF = fj >> 1, fodd = fj & 1;
    const int mrb = pos * 32 + (lane >> 2);            // batch-row base
    const int co = 2 * (lane & 3);
    const int jj = tid & 7;                            // elementwise col
    const int eb = tid >> 3;                           // elementwise batch (0..31)

    float c_state[2] = {0.f, 0.f};

    // xp prefetch for step 0
    float xpv[2][4];
#pragma unroll
    for (int p = 0; p < 2; p++) {
        const float* xq = g_xp + ((size_t)(eb + p * 32) * Tt + 0) * FH + j0 + jj;
#pragma unroll
        for (int g = 0; g < 4; g++) xpv[p][g] = xq[g * Hh];
    }

    for (int t = 0; t < Tt; t++) {
        const unsigned* rdH = g_shHi + (t & 1) * 32768;
        const unsigned* rdL = g_shLo + (t & 1) * 32768;

        float cA[2][4][4], cB[2][4][4], cC[2][4][4];
#pragma unroll
        for (int mt = 0; mt < 2; mt++)
#pragma unroll
            for (int nt = 0; nt < 4; nt++)
#pragma unroll
                for (int q = 0; q < 4; q++) {
                    cA[mt][nt][q] = 0.f; cB[mt][nt][q] = 0.f; cC[mt][nt][q] = 0.f;
                }

        uint4 pre[4][2];
#pragma unroll
        for (int g = 0; g < 4; g++) {
            const int w0 = fr * 512 + g * 128 + fj * 4;
            pre[g][0] = __ldcg((const uint4*)(rdH + w0));
            pre[g][1] = __ldcg((const uint4*)(rdL + w0));
        }

        for (int r = 0; r < 8; r++) {
            const int buf = r & 1;
            // stage all 4 quarters' 32-k slices (permuted, conflict-free banks)
#pragma unroll
            for (int g = 0; g < 4; g++)
#pragma unroll
                for (int sp = 0; sp < 2; sp++) {
                    unsigned* dst = Hsm + (g * 2 + buf) * HRG + sp * HSP
                                        + kcF * HKC + fr * 10 + fodd;
                    uint4 v = pre[g][sp];
                    dst[0] = v.x; dst[2] = v.y; dst[4] = v.z; dst[6] = v.w;
                }
            __syncthreads();
            if (r < 7) {
#pragma unroll
                for (int g = 0; g < 4; g++) {
                    const int w0 = fr * 512 + g * 128 + (r + 1) * 16 + fj * 4;
                    pre[g][0] = __ldcg((const uint4*)(rdH + w0));
                    pre[g][1] = __ldcg((const uint4*)(rdL + w0));
                }
            }
            // compute this group's 32-k slice
#pragma unroll
            for (int kc = 0; kc < 2; kc++) {
                const int ks = grp * 16 + r * 2 + kc;
                uint32_t aH[2][4], aL[2][4];
                const unsigned* abH = Hsm + (grp * 2 + buf) * HRG + 0 * HSP + kc * HKC;
                const unsigned* abL = Hsm + (grp * 2 + buf) * HRG + 1 * HSP + kc * HKC;
#pragma unroll
                for (int mt = 0; mt < 2; mt++) {
                    const int mr = mrb + mt * 16;
                    uint2 lo = *(const uint2*)(abH + mr * 10 + co);
                    uint2 hi = *(const uint2*)(abH + (mr + 8) * 10 + co);
                    aH[mt][0] = lo.x; aH[mt][2] = lo.y; aH[mt][1] = hi.x; aH[mt][3] = hi.y;
                    uint2 lo2 = *(const uint2*)(abL + mr * 10 + co);
                    uint2 hi2 = *(const uint2*)(abL + (mr + 8) * 10 + co);
                    aL[mt][0] = lo2.x; aL[mt][2] = lo2.y; aL[mt][1] = hi2.x; aL[mt][3] = hi2.y;
                }
#pragma unroll
                for (int nt = 0; nt < 4; nt++) {
                    const int n = nt * 8 + (lane >> 2);
                    uint2 bH = *(const uint2*)(WsH + n * WST + ks * 8 + co);
                    uint2 bL = *(const uint2*)(WsL + n * WST + ks * 8 + co);
                    uint32_t bh2[2] = {bH.x, bH.y};
                    uint32_t bl2[2] = {bL.x, bL.y};
#pragma unroll
                    for (int mt = 0; mt < 2; mt++) {
                        mma_bf16(cA[mt][nt], aH[mt], bh2);
                        mma_bf16(cB[mt][nt], aH[mt], bl2);
                        mma_bf16(cC[mt][nt], aL[mt], bh2);
                    }
                }
            }
        }

        // ---- K-partial reduction into aliased Gs (buf0 regions are free:
        //      last compute round r=7 reads only buf1 regions).
        float* gdst = (grp >> 1) ? Gs1 : Gs0;
        if ((grp & 1) == 0) {
#pragma unroll
            for (int mt = 0; mt < 2; mt++) {
                const int m = mrb + mt * 16;
#pragma unroll
                for (int nt = 0; nt < 4; nt++) {
                    const int n = nt * 8 + co;
                    float s0 = cA[mt][nt][0] + cB[mt][nt][0] + cC[mt][nt][0];
                    float s1 = cA[mt][nt][1] + cB[mt][nt][1] + cC[mt][nt][1];
                    float s2 = cA[mt][nt][2] + cB[mt][nt][2] + cC[mt][nt][2];
                    float s3 = cA[mt][nt][3] + cB[mt][nt][3] + cC[mt][nt][3];
                    *(float2*)&gdst[m * 34 + n]       = make_float2(s0, s1);
                    *(float2*)&gdst[(m + 8) * 34 + n] = make_float2(s2, s3);
                }
            }
        }
        __syncthreads();
        if ((grp & 1) == 1) {
#pragma unroll
            for (int mt = 0; mt < 2; mt++) {
                const int m = mrb + mt * 16;
#pragma unroll
                for (int nt = 0; nt < 4; nt++) {
                    const int n = nt * 8 + co;
                    float s0 = cA[mt][nt][0] + cB[mt][nt][0] + cC[mt][nt][0];
                    float s1 = cA[mt][nt][1] + cB[mt][nt][1] + cC[mt][nt][1];
                    float s2 = cA[mt][nt][2] + cB[mt][nt][2] + cC[mt][nt][2];
                    float s3 = cA[mt][nt][3] + cB[mt][nt][3] + cC[mt][nt][3];
                    float2 v0 = *(float2*)&gdst[m * 34 + n];
                    float2 v1 = *(float2*)&gdst[(m + 8) * 34 + n];
                    v0.x += s0; v0.y += s1; v1.x += s2; v1.y += s3;
                    *(float2*)&gdst[m * 34 + n]       = v0;
                    *(float2*)&gdst[(m + 8) * 34 + n] = v1;
                }
            }
        }
        __syncthreads();

        // Elementwise LSTM update (coalesced: lanes sweep jj for fixed b).
        unsigned short* wHs = (unsigned short*)g_shHi + ((t & 1) ^ 1) * 65536;
        unsigned short* wLs = (unsigned short*)g_shLo + ((t & 1) ^ 1) * 65536;
        unsigned short* sqH = (unsigned short*)g_seqHi;
        unsigned short* sqL = (unsigned short*)g_seqLo;
#pragma unroll
        for (int p = 0; p < 2; p++) {
            const int b = eb + p * 32;
            float gi = Gs0[b * 34 + jj]      + Gs1[b * 34 + jj]      + xpv[p][0];
            float gf = Gs0[b * 34 + 8 + jj]  + Gs1[b * 34 + 8 + jj]  + xpv[p][1];
            float gg = Gs0[b * 34 + 16 + jj] + Gs1[b * 34 + 16 + jj] + xpv[p][2];
            float go = Gs0[b * 34 + 24 + jj] + Gs1[b * 34 + 24 + jj] + xpv[p][3];
            float si = 1.f / (1.f + expf(-gi));
            float sf = 1.f / (1.f + expf(-gf));
            float so = 1.f / (1.f + expf(-go));
            float cn = sf * c_state[p] + si * tanhf(gg);
            c_state[p] = cn;
            float hv = so * tanhf(cn);
            __nv_bfloat16 hh = __float2bfloat16_rn(hv);
            __nv_bfloat16 hl = __float2bfloat16_rn(hv - __bfloat162float(hh));
            const int ji = j0 + jj;
            wHs[b * 1024 + ji] = __bfloat16_as_ushort(hh);
            wLs[b * 1024 + ji] = __bfloat16_as_ushort(hl);
            const size_t sidx = ((size_t)b * Tt + t) * 1024 + ji;
            sqH[sidx] = __bfloat16_as_ushort(hh);
            sqL[sidx] = __bfloat16_as_ushort(hl);
        }

        // Prefetch xp for step t+1 (h-independent) so its DRAM latency hides
        // under the grid-barrier wait.
        if (t + 1 < Tt) {
#pragma unroll
            for (int p = 0; p < 2; p++) {
                const float* xq = g_xp + ((size_t)(eb + p * 32) * Tt + (t + 1)) * FH + j0 + jj;
#pragma unroll
                for (int g = 0; g < 4; g++) xpv[p][g] = xq[g * Hh];
            }
        }

        // Grid barrier: monotonic counter, all 128 blocks resident.
        __threadfence();
        __syncthreads();
        if (tid == 0) {
            atomicAdd(&g_bar, 1u);
            const unsigned target = 128u * (unsigned)(t + 1);
            while (*(volatile unsigned*)&g_bar < target) { }
        }
        __syncthreads();
    }
}

__global__ void fc_kernel(const float* __restrict__ fw, const float* __restrict__ fb,
                          float* __restrict__ out)
{
    __shared__ float red[256];
    int b = blockIdx.x, tid = threadIdx.x;
    const unsigned short* sqH = (const unsigned short*)g_seqHi;
    const unsigned short* sqL = (const unsigned short*)g_seqLo;
    const size_t base = ((size_t)b * Tt + (Tt - 1)) * 1024;
    float s = 0.f;
    for (int j = tid; j < Hh; j += 256) {
        float hv = __bfloat162float(__ushort_as_bfloat16(sqH[base + j]))
                 + __bfloat162float(__ushort_as_bfloat16(sqL[base + j]));
        s += hv * fw[j];
    }
    red[tid] = s;
    __syncthreads();
    for (int o = 128; o > 0; o >>= 1) {
        if (tid < o) red[tid] += red[tid + o];
        __syncthreads();
    }
    if (tid == 0) out[b] = red[0] + fb[0];
}

extern "C" void kernel_launch(void* const* d_in, const int* in_sizes, int n_in,
                              void* d_out, int out_size)
{
    const float* x      = (const float*)d_in[0];
    const float* Wih[3] = {(const float*)d_in[1], (const float*)d_in[2], (const float*)d_in[3]};
    const float* Whh    = (const float*)d_in[4];   // [3][4096][1024]
    const float* bih    = (const float*)d_in[5];   // [3][4096]
    const float* bhh    = (const float*)d_in[6];   // [3][4096]
    const float* fcw    = (const float*)d_in[7];   // [1][1024]
    const float* fcb    = (const float*)d_in[8];   // [1]
    float* out = (float*)d_out;

    cudaFuncSetAttribute(lstm_persist,
                         cudaFuncAttributeMaxDynamicSharedMemorySize, PSMEM);

    for (int l = 0; l < 3; l++) {
        const int K = l ? Hh : 128;
        if (l == 0) {
            const int nA4 = Mm * 128 / 4;
            split_A<<<(nA4 + 255) / 256, 256>>>(x, nA4);
        }
        const int nW4 = FH * K / 4;
        split_W<<<(nW4 + 255) / 256, 256>>>(Wih[l], nW4);
        gemm_bf<<<dim3(64, 256), 256>>>(K, bih + l * FH, bhh + l * FH);
        lstm_persist<<<128, 256, PSMEM>>>(Whh + (size_t)l * FH * Hh);
    }
    fc_kernel<<<64, 256>>>(fcw, fcb, out);
}

// round 17
// speedup vs baseline: 2.4366x; 1.0456x over previous
#include <cuda_runtime.h>
#include <cuda_bf16.h>
#include <math.h>
#include <stdint.h>
#include <stddef.h>

#define Hh 1024
#define FH 4096
#define Bb 64
#define Tt 512
#define Mm 32768   // B*T

// Scratch (device globals: no runtime allocation).
__device__ float g_xp[(size_t)Mm * FH];             // gate preactivations
__device__ unsigned g_seqHi[(size_t)Mm * Hh / 2];   // bf16 hidden seq (hi), word-packed
__device__ unsigned g_seqLo[(size_t)Mm * Hh / 2];   // bf16 hidden seq (lo)
__device__ unsigned g_Whi[(size_t)FH * Hh / 2];     // bf16-pair split of W_ih (hi)
__device__ unsigned g_Wlo[(size_t)FH * Hh / 2];     // bf16-pair split of W_ih (lo)
__device__ unsigned g_shHi[2 * 32768];              // per-step h (hi), 2 buffers
__device__ unsigned g_shLo[2 * 32768];              // per-step h (lo)
__device__ unsigned g_bar;                          // grid-barrier counter

// bf16 m16n8k16 warp MMA (plain PTX ISA, compiles on compute_103):
__device__ __forceinline__ void mma_bf16(float* c, const uint32_t* a, const uint32_t* b) {
    asm volatile(
        "mma.sync.aligned.m16n8k16.row.col.f32.bf16.bf16.f32 "
        "{%0,%1,%2,%3}, {%4,%5,%6,%7}, {%8,%9}, {%0,%1,%2,%3};"
        : "+f"(c[0]), "+f"(c[1]), "+f"(c[2]), "+f"(c[3])
        : "r"(a[0]), "r"(a[1]), "r"(a[2]), "r"(a[3]), "r"(b[0]), "r"(b[1]));
}

__device__ __forceinline__ unsigned packbf(float a, float b, float& ra, float& rb) {
    __nv_bfloat16 ha = __float2bfloat16_rn(a);
    __nv_bfloat16 hb = __float2bfloat16_rn(b);
    ra = a - __bfloat162float(ha);
    rb = b - __bfloat162float(hb);
    return (unsigned)__bfloat16_as_ushort(ha) |
           ((unsigned)__bfloat16_as_ushort(hb) << 16);
}
__device__ __forceinline__ unsigned packbf2(float a, float b) {
    __nv_bfloat16 ha = __float2bfloat16_rn(a);
    __nv_bfloat16 hb = __float2bfloat16_rn(b);
    return (unsigned)__bfloat16_as_ushort(ha) |
           ((unsigned)__bfloat16_as_ushort(hb) << 16);
}

// ---------------------------------------------------------------------------
// Split kernels. split_W also does per-layer init (barrier reset + step-buf0
// zeroing) so lstm_persist stays at global launch index 3 for ncu.
// ---------------------------------------------------------------------------
__global__ void split_A(const float* __restrict__ x, int n4)  // layer 0 only
{
    int i = blockIdx.x * blockDim.x + threadIdx.x;
    if (i < n4) {
        float4 v = ((const float4*)x)[i];
        float rx, ry, rz, rw;
        uint2 h, l;
        h.x = packbf(v.x, v.y, rx, ry);
        h.y = packbf(v.z, v.w, rz, rw);
        l.x = packbf2(rx, ry);
        l.y = packbf2(rz, rw);
        ((uint2*)g_seqHi)[i] = h;
        ((uint2*)g_seqLo)[i] = l;
    }
}
__global__ void split_W(const float* __restrict__ W, int n4)
{
    int i = blockIdx.x * blockDim.x + threadIdx.x;
    if (i == 0) g_bar = 0u;
    if (i < 32768) { g_shHi[i] = 0u; g_shLo[i] = 0u; }   // zero step-buffer 0
    if (i < n4) {
        float4 v = ((const float4*)W)[i];
        float rx, ry, rz, rw;
        uint2 h, l;
        h.x = packbf(v.x, v.y, rx, ry);
        h.y = packbf(v.z, v.w, rz, rw);
        l.x = packbf2(rx, ry);
        l.y = packbf2(rz, rw);
        ((uint2*)g_Whi)[i] = h;
        ((uint2*)g_Wlo)[i] = l;
    }
}

// ---------------------------------------------------------------------------
// Projection GEMM via bf16 m16n8k16 mma.sync (validated R12/R14 kernel).
// ---------------------------------------------------------------------------
#define RS 10   // smem row stride (words)

__global__ __launch_bounds__(256) void gemm_bf(int K,
    const float* __restrict__ bi, const float* __restrict__ bh)
{
    __shared__ __align__(16) unsigned As[2 * 2 * 128 * RS];
    __shared__ __align__(16) unsigned Ws[2 * 2 * 64 * RS];

    const int tid = threadIdx.x;
    const int lane = tid & 31, wid = tid >> 5;
    const int wm = wid & 3, wn = wid >> 2;
    const int m0 = blockIdx.y << 7, n0 = blockIdx.x << 6;
    const int Kw = K >> 1;

    const int arow = tid >> 1, akq = (tid & 1) * 8;
    const int wrow = tid >> 2, wkq = (tid & 3) * 4;
    const unsigned* pA[2] = { g_seqHi + (size_t)(m0 + arow) * Kw + akq,
                              g_seqLo + (size_t)(m0 + arow) * Kw + akq };
    const unsigned* pW[2] = { g_Whi + (size_t)(n0 + wrow) * Kw + wkq,
                              g_Wlo + (size_t)(n0 + wrow) * Kw + wkq };

    float acc[2][4][4];
#pragma unroll
    for (int mt = 0; mt < 2; mt++)
#pragma unroll
        for (int nt = 0; nt < 4; nt++)
#pragma unroll
            for (int q = 0; q < 4; q++) acc[mt][nt][q] = 0.f;

    uint4 pa[2][2], pw[2];
#pragma unroll
    for (int sp = 0; sp < 2; sp++) {
        pa[sp][0] = *(const uint4*)(pA[sp]);
        pa[sp][1] = *(const uint4*)(pA[sp] + 4);
        pw[sp]    = *(const uint4*)(pW[sp]);
    }

    const int nch = K >> 5;
    for (int ch = 0; ch < nch; ch++) {
        __syncthreads();
#pragma unroll
        for (int sp = 0; sp < 2; sp++) {
#pragma unroll
            for (int f = 0; f < 2; f++) {
                const int kb = akq + f * 4;
                const int kc = kb >> 3, podd = (kb & 4) ? 1 : 0;
                unsigned* dst = &As[((sp * 2 + kc) * 128 + arow) * RS + podd];
                const unsigned* v = (const unsigned*)&pa[sp][f];
                dst[0] = v[0]; dst[2] = v[1]; dst[4] = v[2]; dst[6] = v[3];
            }
            {
                const int kc = wkq >> 3, podd = (wkq & 4) ? 1 : 0;
                unsigned* dst = &Ws[((sp * 2 + kc) * 64 + wrow) * RS + podd];
                const unsigned* v = (const unsigned*)&pw[sp];
                dst[0] = v[0]; dst[2] = v[1]; dst[4] = v[2]; dst[6] = v[3];
            }
        }
        __syncthreads();
        if (ch + 1 < nch) {
#pragma unroll
            for (int sp = 0; sp < 2; sp++) {
                pa[sp][0] = *(const uint4*)(pA[sp] + (ch + 1) * 16);
                pa[sp][1] = *(const uint4*)(pA[sp] + (ch + 1) * 16 + 4);
                pw[sp]    = *(const uint4*)(pW[sp] + (ch + 1) * 16);
            }
        }
#pragma unroll
        for (int kc = 0; kc < 2; kc++) {
            uint32_t af[2][2][4];
            uint32_t bf[2][4][2];
            const int co = 2 * (lane & 3);
#pragma unroll
            for (int sp = 0; sp < 2; sp++) {
#pragma unroll
                for (int mt = 0; mt < 2; mt++) {
                    const int mr = wm * 32 + mt * 16 + (lane >> 2);
                    uint2 lo = *(const uint2*)&As[((sp * 2 + kc) * 128 + mr) * RS + co];
                    uint2 hi = *(const uint2*)&As[((sp * 2 + kc) * 128 + mr + 8) * RS + co];
                    af[sp][mt][0] = lo.x;
                    af[sp][mt][2] = lo.y;
                    af[sp][mt][1] = hi.x;
                    af[sp][mt][3] = hi.y;
                }
#pragma unroll
                for (int nt = 0; nt < 4; nt++) {
                    const int nr = wn * 32 + nt * 8 + (lane >> 2);
                    uint2 bv = *(const uint2*)&Ws[((sp * 2 + kc) * 64 + nr) * RS + co];
                    bf[sp][nt][0] = bv.x;
                    bf[sp][nt][1] = bv.y;
                }
            }
#pragma unroll
            for (int mt = 0; mt < 2; mt++)
#pragma unroll
                for (int nt = 0; nt < 4; nt++) {
                    mma_bf16(acc[mt][nt], af[0][mt], bf[0][nt]);
                    mma_bf16(acc[mt][nt], af[0][mt], bf[1][nt]);
                    mma_bf16(acc[mt][nt], af[1][mt], bf[0][nt]);
                }
        }
    }

#pragma unroll
    for (int mt = 0; mt < 2; mt++) {
        const int m = m0 + wm * 32 + mt * 16 + (lane >> 2);
#pragma unroll
        for (int nt = 0; nt < 4; nt++) {
            const int n = n0 + wn * 32 + nt * 8 + 2 * (lane & 3);
            const float b0 = __ldg(&bi[n]) + __ldg(&bh[n]);
            const float b1 = __ldg(&bi[n + 1]) + __ldg(&bh[n + 1]);
            float2 o0 = make_float2(acc[mt][nt][0] + b0, acc[mt][nt][1] + b1);
            float2 o1 = make_float2(acc[mt][nt][2] + b0, acc[mt][nt][3] + b1);
            *(float2*)(g_xp + (size_t)m * FH + n)       = o0;
            *(float2*)(g_xp + (size_t)(m + 8) * FH + n) = o1;
        }
    }
}

// ---------------------------------------------------------------------------
// Persistent HMMA recurrence, v4: transposed (p-slot-major) SMEM layout.
// Chunk (16 k) = 4 p-slots x (64 rows x 2 words). Slot strides: Hsm 136,
// W 72 (both ==8 mod 32); kc stride 560 (==16 mod 32). Verified:
//  - staging STS.32: banks 2fr + {0,1,16,17} -> 1 phase (byte floor)
//  - every fragment LDS.64: banks 8c + 2q -> exactly 2 wf (byte floor)
//    (was 2-way conflicted in v3 -> frag wf halves: 8192 -> 4096 /step)
// Merged correction accumulator (cB += aH*bL and aL*bH): 2 acc sets.
// Per-group Gs buffers (4x, aliased on buf0 staging regions which round 7
// never touches) -> single sync, no 2-phase reduction.
// ---------------------------------------------------------------------------
#define WPS 72                         // W p-slot stride (words)
#define WKC 288                        // W per-kc region (4*72)
#define WSPB 18432                     // W sp block (64*288)
#define HPS 136                        // Hsm p-slot stride
#define HKCS 560                       // Hsm kc stride (==16 mod 32)
#define HSPS 1120
#define HBUFS 2240
#define HGS 4480
#define HSM_OFF (2 * WSPB)             // 36864 words
#define PSMEM ((HSM_OFF + 4 * HGS) * 4)   // 219136 B

__global__ __launch_bounds__(256, 1) void lstm_persist(const float* __restrict__ Whh)
{
    extern __shared__ unsigned su[];
    unsigned* WsH = su;                    // [kc 64][p 4][n*2+j]
    unsigned* WsL = su + WSPB;
    unsigned* Hsm = su + HSM_OFF;          // [g][buf][sp][kc][p][row*2+j]

    const int tid = threadIdx.x;
    const int lane = tid & 31, wid = tid >> 5;
    const int grp = wid >> 1;                          // k-quarter 0..3
    const int pos = wid & 1;                           // batch half
    const int j0 = blockIdx.x << 3;

    // --- one-time W slice load + bf16 split (transposed p-slot store) ---
    {
        const int lw = tid >> 3;                       // local gate row 0..31
        const int ke = (tid & 7) * 128;
        const float* wp = Whh + (size_t)((lw >> 3) * Hh + j0 + (lw & 7)) * Hh + ke;
#pragma unroll 4
        for (int i = 0; i < 32; i++) {
            float4 v = *(const float4*)(wp + i * 4);
            float rx, ry, rz, rw;
            unsigned h0 = packbf(v.x, v.y, rx, ry);
            unsigned h1 = packbf(v.z, v.w, rz, rw);
            unsigned l0 = packbf2(rx, ry);
            unsigned l1 = packbf2(rz, rw);
            const int kp0 = (ke >> 1) + 2 * i;         // even k-pair index
            const int kc = kp0 >> 3;
            const int pw0 = kp0 & 7;                   // in {0,2,4,6}
            const int p0 = pw0 & 3, jj0 = pw0 >> 2;
            const int pw1 = pw0 + 1;
            const int p1 = pw1 & 3, jj1 = pw1 >> 2;
            const int base = kc * WKC + lw * 2;
            WsH[base + p0 * WPS + jj0] = h0;
            WsH[base + p1 * WPS + jj1] = h1;
            WsL[base + p0 * WPS + jj0] = l0;
            WsL[base + p1 * WPS + jj1] = l1;
        }
    }
    __syncthreads();

    const int fr = tid >> 2, fj = tid & 3;             // h-fill map
    const int kcF = fj >> 1, fodd = fj & 1;
    const int mrb = pos * 32 + (lane >> 2);            // batch-row base
    const int cc = lane & 3;                           // fragment p-slot
    const int jj = tid & 7;                            // elementwise col
    const int eb = tid >> 3;                           // elementwise batch (0..31)

    float c_state[2] = {0.f, 0.f};

    // xp prefetch for step 0
    float xpv[2][4];
#pragma unroll
    for (int p = 0; p < 2; p++) {
        const float* xq = g_xp + ((size_t)(eb + p * 32) * Tt + 0) * FH + j0 + jj;
#pragma unroll
        for (int g = 0; g < 4; g++) xpv[p][g] = xq[g * Hh];
    }

    for (int t = 0; t < Tt; t++) {
        const unsigned* rdH = g_shHi + (t & 1) * 32768;
        const unsigned* rdL = g_shLo + (t & 1) * 32768;

        float cA[2][4][4], cB[2][4][4];
#pragma unroll
        for (int mt = 0; mt < 2; mt++)
#pragma unroll
            for (int nt = 0; nt < 4; nt++)
#pragma unroll
                for (int q = 0; q < 4; q++) { cA[mt][nt][q] = 0.f; cB[mt][nt][q] = 0.f; }

        uint4 pre[4][2];
#pragma unroll
        for (int g = 0; g < 4; g++) {
            const int w0 = fr * 512 + g * 128 + fj * 4;
            pre[g][0] = __ldcg((const uint4*)(rdH + w0));
            pre[g][1] = __ldcg((const uint4*)(rdL + w0));
        }

        for (int r = 0; r < 8; r++) {
            const int buf = r & 1;
            // stage (transposed p-slot layout; conflict-free STS.32)
#pragma unroll
            for (int g = 0; g < 4; g++)
#pragma unroll
                for (int sp = 0; sp < 2; sp++) {
                    unsigned* dst = Hsm + g * HGS + buf * HBUFS + sp * HSPS
                                        + kcF * HKCS + fr * 2 + fodd;
                    uint4 v = pre[g][sp];
                    dst[0]       = v.x;
                    dst[HPS]     = v.y;
                    dst[2 * HPS] = v.z;
                    dst[3 * HPS] = v.w;
                }
            __syncthreads();
            if (r < 7) {
#pragma unroll
                for (int g = 0; g < 4; g++) {
                    const int w0 = fr * 512 + g * 128 + (r + 1) * 16 + fj * 4;
                    pre[g][0] = __ldcg((const uint4*)(rdH + w0));
                    pre[g][1] = __ldcg((const uint4*)(rdL + w0));
                }
            }
            // compute this group's 32-k slice
#pragma unroll
            for (int kc = 0; kc < 2; kc++) {
                const int ks = grp * 16 + r * 2 + kc;
                const unsigned* abH = Hsm + grp * HGS + buf * HBUFS + kc * HKCS + cc * HPS;
                const unsigned* abL = abH + HSPS;
                uint32_t aH[2][4], aL[2][4];
#pragma unroll
                for (int mt = 0; mt < 2; mt++) {
                    const int mr2 = (mrb + mt * 16) * 2;
                    uint2 lo = *(const uint2*)(abH + mr2);
                    uint2 hi = *(const uint2*)(abH + mr2 + 16);
                    aH[mt][0] = lo.x; aH[mt][2] = lo.y; aH[mt][1] = hi.x; aH[mt][3] = hi.y;
                    uint2 lo2 = *(const uint2*)(abL + mr2);
                    uint2 hi2 = *(const uint2*)(abL + mr2 + 16);
                    aL[mt][0] = lo2.x; aL[mt][2] = lo2.y; aL[mt][1] = hi2.x; aL[mt][3] = hi2.y;
                }
                const unsigned* wbase = WsH + ks * WKC + cc * WPS;
                const unsigned* wbaseL = WsL + ks * WKC + cc * WPS;
#pragma unroll
                for (int nt = 0; nt < 4; nt++) {
                    const int n2 = (nt * 8 + (lane >> 2)) * 2;
                    uint2 bH = *(const uint2*)(wbase + n2);
                    uint2 bL = *(const uint2*)(wbaseL + n2);
                    uint32_t bh2[2] = {bH.x, bH.y};
                    uint32_t bl2[2] = {bL.x, bL.y};
#pragma unroll
                    for (int mt = 0; mt < 2; mt++) {
                        mma_bf16(cA[mt][nt], aH[mt], bh2);
                        mma_bf16(cB[mt][nt], aH[mt], bl2);
                        mma_bf16(cB[mt][nt], aL[mt], bh2);
                    }
                }
            }
        }

        // ---- per-group Gs write (aliased on buf0 regions; round 7 used buf1)
        {
            float* gq = (float*)(Hsm + grp * HGS);
#pragma unroll
            for (int mt = 0; mt < 2; mt++) {
                const int m = mrb + mt * 16;
#pragma unroll
                for (int nt = 0; nt < 4; nt++) {
                    const int n = nt * 8 + 2 * (lane & 3);
                    float s0 = cA[mt][nt][0] + cB[mt][nt][0];
                    float s1 = cA[mt][nt][1] + cB[mt][nt][1];
                    float s2 = cA[mt][nt][2] + cB[mt][nt][2];
                    float s3 = cA[mt][nt][3] + cB[mt][nt][3];
                    *(float2*)&gq[m * 34 + n]       = make_float2(s0, s1);
                    *(float2*)&gq[(m + 8) * 34 + n] = make_float2(s2, s3);
                }
            }
        }
        __syncthreads();

        // Elementwise LSTM update (sums the 4 group partials).
        unsigned short* wHs = (unsigned short*)g_shHi + ((t & 1) ^ 1) * 65536;
        unsigned short* wLs = (unsigned short*)g_shLo + ((t & 1) ^ 1) * 65536;
        unsigned short* sqH = (unsigned short*)g_seqHi;
        unsigned short* sqL = (unsigned short*)g_seqLo;
        const float* G0 = (const float*)(Hsm);
        const float* G1 = (const float*)(Hsm + HGS);
        const float* G2 = (const float*)(Hsm + 2 * HGS);
        const float* G3 = (const float*)(Hsm + 3 * HGS);
#pragma unroll
        for (int p = 0; p < 2; p++) {
            const int b = eb + p * 32;
            float gv[4];
#pragma unroll
            for (int g = 0; g < 4; g++) {
                const int o = b * 34 + g * 8 + jj;
                gv[g] = G0[o] + G1[o] + G2[o] + G3[o] + xpv[p][g];
            }
            float si = 1.f / (1.f + expf(-gv[0]));
            float sf = 1.f / (1.f + expf(-gv[1]));
            float so = 1.f / (1.f + expf(-gv[3]));
            float cn = sf * c_state[p] + si * tanhf(gv[2]);
            c_state[p] = cn;
            float hv = so * tanhf(cn);
            __nv_bfloat16 hh = __float2bfloat16_rn(hv);
            __nv_bfloat16 hl = __float2bfloat16_rn(hv - __bfloat162float(hh));
            const int ji = j0 + jj;
            wHs[b * 1024 + ji] = __bfloat16_as_ushort(hh);
            wLs[b * 1024 + ji] = __bfloat16_as_ushort(hl);
            const size_t sidx = ((size_t)b * Tt + t) * 1024 + ji;
            sqH[sidx] = __bfloat16_as_ushort(hh);
            sqL[sidx] = __bfloat16_as_ushort(hl);
        }

        // Prefetch xp(t+1) so its DRAM latency hides under the barrier wait.
        if (t + 1 < Tt) {
#pragma unroll
            for (int p = 0; p < 2; p++) {
                const float* xq = g_xp + ((size_t)(eb + p * 32) * Tt + (t + 1)) * FH + j0 + jj;
#pragma unroll
                for (int g = 0; g < 4; g++) xpv[p][g] = xq[g * Hh];
            }
        }

        // Grid barrier: monotonic counter, all 128 blocks resident.
        __threadfence();
        __syncthreads();
        if (tid == 0) {
            atomicAdd(&g_bar, 1u);
            const unsigned target = 128u * (unsigned)(t + 1);
            while (*(volatile unsigned*)&g_bar < target) { }
        }
        __syncthreads();
    }
}

__global__ void fc_kernel(const float* __restrict__ fw, const float* __restrict__ fb,
                          float* __restrict__ out)
{
    __shared__ float red[256];
    int b = blockIdx.x, tid = threadIdx.x;
    const unsigned short* sqH = (const unsigned short*)g_seqHi;
    const unsigned short* sqL = (const unsigned short*)g_seqLo;
    const size_t base = ((size_t)b * Tt + (Tt - 1)) * 1024;
    float s = 0.f;
    for (int j = tid; j < Hh; j += 256) {
        float hv = __bfloat162float(__ushort_as_bfloat16(sqH[base + j]))
                 + __bfloat162float(__ushort_as_bfloat16(sqL[base + j]));
        s += hv * fw[j];
    }
    red[tid] = s;
    __syncthreads();
    for (int o = 128; o > 0; o >>= 1) {
        if (tid < o) red[tid] += red[tid + o];
        __syncthreads();
    }
    if (tid == 0) out[b] = red[0] + fb[0];
}

extern "C" void kernel_launch(void* const* d_in, const int* in_sizes, int n_in,
                              void* d_out, int out_size)
{
    const float* x      = (const float*)d_in[0];
    const float* Wih[3] = {(const float*)d_in[1], (const float*)d_in[2], (const float*)d_in[3]};
    const float* Whh    = (const float*)d_in[4];   // [3][4096][1024]
    const float* bih    = (const float*)d_in[5];   // [3][4096]
    const float* bhh    = (const float*)d_in[6];   // [3][4096]
    const float* fcw    = (const float*)d_in[7];   // [1][1024]
    const float* fcb    = (const float*)d_in[8];   // [1]
    float* out = (float*)d_out;

    cudaFuncSetAttribute(lstm_persist,
                         cudaFuncAttributeMaxDynamicSharedMemorySize, PSMEM);

    for (int l = 0; l < 3; l++) {
        const int K = l ? Hh : 128;
        if (l == 0) {
            const int nA4 = Mm * 128 / 4;
            split_A<<<(nA4 + 255) / 256, 256>>>(x, nA4);
        }
        const int nW4 = FH * K / 4;
        split_W<<<(nW4 + 255) / 256, 256>>>(Wih[l], nW4);
        gemm_bf<<<dim3(64, 256), 256>>>(K, bih + l * FH, bhh + l * FH);
        lstm_persist<<<128, 256, PSMEM>>>(Whh + (size_t)l * FH * Hh);
    }
    fc_kernel<<<64, 256>>>(fcw, fcb, out);
}